// round 13
// baseline (speedup 1.0000x reference)
#include <cuda_runtime.h>
#include <cuda_bf16.h>
#include <math.h>
#include <stdint.h>

#define DM    2048
#define SEQ   2048
#define BATCH 2
#define NH    32
#define NG    8
#define DH    64
#define MROWS (BATCH*SEQ)   // 4096
#define NQKV  3072

// bid layout of the single fused launch
#define B_WQKV   0          // 384: Wqkv transpose (24 col-blocks x 16 k-slices)
#define B_WO     384        // 256: Wo transpose (16 x 16)
#define B_ASP    640        // 512: hs split (32 row-blocks x 16 slices)
#define B_ROPE   1152       // 8:   rope table
#define B_QKV    1160       // 768: QKV gemm tiles
#define B_ATT    1928       // 1024: attention
#define B_OUT    2952       // 512: out-proj
#define B_TOTAL  3464

// ---------------- scratch (__device__ globals; no allocs allowed) ----------
__device__ __nv_bfloat16 g_ah[(size_t)MROWS*DM];   // A split (hs, later ctx)
__device__ __nv_bfloat16 g_al[(size_t)MROWS*DM];
__device__ __nv_bfloat16 g_wch[(size_t)NQKV*DM], g_wcl[(size_t)NQKV*DM];
__device__ __nv_bfloat16 g_woh[(size_t)DM*DM],   g_wol[(size_t)DM*DM];
__device__ __nv_bfloat16 g_qh[(size_t)BATCH*NH*SEQ*DH], g_ql[(size_t)BATCH*NH*SEQ*DH];
__device__ __nv_bfloat16 g_kh[(size_t)BATCH*NG*SEQ*DH], g_kl[(size_t)BATCH*NG*SEQ*DH];
__device__ __nv_bfloat16 g_vh[(size_t)BATCH*NG*SEQ*DH], g_vl[(size_t)BATCH*NG*SEQ*DH];
__device__ float2 g_rope[SEQ * 32];
// producer/consumer flags (static-init 0; self-cleaned by last out-proj CTA)
__device__ int g_flagW[24];    // Wqkv col-block ready (target 16)
__device__ int g_flagWo[16];   // Wo col-block ready (target 16)
__device__ int g_flagAsp[32];  // hs-split row-block ready (target 16)
__device__ int g_flagR;        // rope ready (target 8)
__device__ int g_flagM[32];    // QKV row-block done (target 24)
__device__ int g_flagA[32];    // attention row-block done (target 32)
__device__ int g_done;         // out-proj completion counter

// ---------------- helpers ---------------------------------------------------
__device__ __forceinline__ uint32_t smem_u32(const void* p) {
    uint32_t a;
    asm("{ .reg .u64 t; cvta.to.shared.u64 t, %1; cvt.u32.u64 %0, t; }" : "=r"(a) : "l"(p));
    return a;
}
__device__ __forceinline__ void ldsm4(uint32_t* r, uint32_t addr) {
    asm volatile("ldmatrix.sync.aligned.m8n8.x4.shared.b16 {%0,%1,%2,%3}, [%4];"
                 : "=r"(r[0]), "=r"(r[1]), "=r"(r[2]), "=r"(r[3]) : "r"(addr));
}
__device__ __forceinline__ void ldsm4t(uint32_t* r, uint32_t addr) {
    asm volatile("ldmatrix.sync.aligned.m8n8.x4.trans.shared.b16 {%0,%1,%2,%3}, [%4];"
                 : "=r"(r[0]), "=r"(r[1]), "=r"(r[2]), "=r"(r[3]) : "r"(addr));
}
__device__ __forceinline__ void mma16816(float* c, const uint32_t* a, const uint32_t* b) {
    asm volatile("mma.sync.aligned.m16n8k16.row.col.f32.bf16.bf16.f32 "
                 "{%0,%1,%2,%3}, {%4,%5,%6,%7}, {%8,%9}, {%0,%1,%2,%3};"
                 : "+f"(c[0]), "+f"(c[1]), "+f"(c[2]), "+f"(c[3])
                 : "r"(a[0]), "r"(a[1]), "r"(a[2]), "r"(a[3]), "r"(b[0]), "r"(b[1]));
}
#define CP_ASYNC16(s, g) \
    asm volatile("cp.async.cg.shared.global [%0], [%1], 16;" :: "r"(s), "l"(g))
#define CP_COMMIT() asm volatile("cp.async.commit_group;" ::: "memory")
#define CP_WAIT1()  asm volatile("cp.async.wait_group 1;" ::: "memory")

__device__ __forceinline__ uint32_t packbf(float lo, float hi) {
    __nv_bfloat162 t = __floats2bfloat162_rn(lo, hi);
    return *reinterpret_cast<uint32_t*>(&t);
}
__device__ __forceinline__ float ex2f(float x) {
    float r;
    asm("ex2.approx.ftz.f32 %0, %1;" : "=f"(r) : "f"(x));
    return r;
}
__device__ __forceinline__ void split_pair(float p0, float p1,
                                           uint32_t& hi, uint32_t& lo) {
    uint32_t b0 = __float_as_uint(p0), b1 = __float_as_uint(p1);
    asm("prmt.b32 %0, %1, %2, 0x7632;" : "=r"(hi) : "r"(b0), "r"(b1));
    float h0 = __uint_as_float(b0 & 0xffff0000u);
    float h1 = __uint_as_float(b1 & 0xffff0000u);
    lo = packbf(p0 - h0, p1 - h1);
}
__device__ __forceinline__ float softmax_p(float sv) {
    const float s2 = sv * sv;
    const float P = fmaf(s2, fmaf(s2, 2.3748002e-7f, -5.3433150e-4f), 1.44269504f);
    return ex2f(fmaf(sv, P, -43.2808512f));
}
__device__ __forceinline__ void spin_ge(const int* f, int target) {
    const volatile int* vf = (const volatile int*)f;
    while (*vf < target) __nanosleep(128);
    __threadfence();
}

// ---------------------------------------------------------------------------
// bf16x3 HMMA GEMM tile: 128x128 CTA tile, BK=32, 3-stage cp.async ring.
// mode 0: fp32 row-major + bias.  mode 3: combined QKV epilogue.
// ---------------------------------------------------------------------------
__device__ __forceinline__ void gemm_tile(
    const __nv_bfloat16* __restrict__ Ah, const __nv_bfloat16* __restrict__ Al,
    const __nv_bfloat16* __restrict__ Bh, const __nv_bfloat16* __restrict__ Bl,
    float* __restrict__ Cf,
    __nv_bfloat16* __restrict__ Qh, __nv_bfloat16* __restrict__ Ql,
    __nv_bfloat16* __restrict__ Kh, __nv_bfloat16* __restrict__ Kl,
    __nv_bfloat16* __restrict__ Vh, __nv_bfloat16* __restrict__ Vl,
    const float2* __restrict__ rope,
    int Ntot, int mode, const float* __restrict__ bias,
    int m0, int n0, char* smc)
{
    const uint32_t sbase = smem_u32(smc);
    const int tid = threadIdx.x, lane = tid & 31, wid = tid >> 5;
    const int wm = wid >> 2, wn = wid & 3;
    const int fr = tid >> 2;
    const int fc = tid & 3;

    uint32_t offA[4][2], offB[2][2];
#pragma unroll
    for (int mf = 0; mf < 4; mf++)
#pragma unroll
        for (int ks = 0; ks < 2; ks++) {
            int row = wm * 64 + mf * 16 + (lane & 7) + ((lane >> 3) & 1) * 8;
            int ch  = ks * 2 + (lane >> 4);
            offA[mf][ks] = row * 64 + ((ch ^ ((row >> 1) & 3)) << 4);
        }
#pragma unroll
    for (int np = 0; np < 2; np++)
#pragma unroll
        for (int ks = 0; ks < 2; ks++) {
            int row = wn * 32 + np * 16 + (lane & 7) + (lane >> 4) * 8;
            int ch  = ks * 2 + ((lane >> 3) & 1);
            offB[np][ks] = row * 64 + ((ch ^ ((row >> 1) & 3)) << 4);
        }

    float acc[4][4][4];
#pragma unroll
    for (int i = 0; i < 4; i++)
#pragma unroll
        for (int j = 0; j < 4; j++)
#pragma unroll
            for (int l = 0; l < 4; l++) acc[i][j][l] = 0.f;

    auto fill = [&](int kc, int stage) {
        const uint32_t sb = sbase + stage * 32768;
#pragma unroll
        for (int i = 0; i < 2; i++) {
            const int r = fr + i * 64;
            const uint32_t so = r * 64 + ((fc ^ ((r >> 1) & 3)) << 4);
            const size_t gA = (size_t)(m0 + r) * DM + kc * 32 + fc * 8;
            const size_t gB = (size_t)(n0 + r) * DM + kc * 32 + fc * 8;
            CP_ASYNC16(sb +         so, Ah + gA);
            CP_ASYNC16(sb +  8192 + so, Al + gA);
            CP_ASYNC16(sb + 16384 + so, Bh + gB);
            CP_ASYNC16(sb + 24576 + so, Bl + gB);
        }
        CP_COMMIT();
    };

    fill(0, 0);
    fill(1, 1);

    const int NKC = DM / 32;
    int rd = 0, wr = 2;
    for (int kc = 0; kc < NKC; kc++) {
        CP_WAIT1();
        __syncthreads();
        const uint32_t sA = sbase + rd * 32768;
#pragma unroll
        for (int ks = 0; ks < 2; ks++) {
            uint32_t bh[2][4], bl[2][4];
#pragma unroll
            for (int np = 0; np < 2; np++) {
                ldsm4(bh[np], sA + 16384 + offB[np][ks]);
                ldsm4(bl[np], sA + 24576 + offB[np][ks]);
            }
#pragma unroll
            for (int mf = 0; mf < 4; mf++) {
                uint32_t ah[4], al[4];
                ldsm4(ah, sA +        offA[mf][ks]);
                ldsm4(al, sA + 8192 + offA[mf][ks]);
#pragma unroll
                for (int nf = 0; nf < 4; nf++) {
                    const uint32_t* bhp = &bh[nf >> 1][(nf & 1) * 2];
                    const uint32_t* blp = &bl[nf >> 1][(nf & 1) * 2];
                    mma16816(acc[mf][nf], ah, bhp);
                    mma16816(acc[mf][nf], ah, blp);
                    mma16816(acc[mf][nf], al, bhp);
                }
            }
        }
        if (kc + 2 < NKC) fill(kc + 2, wr);
        else CP_COMMIT();
        rd = (rd == 2) ? 0 : rd + 1;
        wr = (wr == 2) ? 0 : wr + 1;
    }

    const int g4 = lane >> 2, t4 = lane & 3;
#pragma unroll
    for (int mf = 0; mf < 4; mf++) {
#pragma unroll
        for (int nf = 0; nf < 4; nf++) {
            const int row = m0 + wm * 64 + mf * 16 + g4;
            const int col = n0 + wn * 32 + nf * 8 + t4 * 2;
            float2 v0 = make_float2(acc[mf][nf][0], acc[mf][nf][1]);
            float2 v1 = make_float2(acc[mf][nf][2], acc[mf][nf][3]);
            if (mode == 0) {
                const float b0 = bias[col], b1 = bias[col + 1];
                v0.x += b0; v0.y += b1; v1.x += b0; v1.y += b1;
                *reinterpret_cast<float2*>(Cf + (size_t)row * Ntot + col)       = v0;
                *reinterpret_cast<float2*>(Cf + (size_t)(row + 8) * Ntot + col) = v1;
            } else {
                __nv_bfloat16 *Oh, *Ol;
                int hh, hcount;
                bool dorope;
                if (col < 2048)      { Oh = Qh; Ol = Ql; hh = col >> 6;          hcount = NH; dorope = true; }
                else if (col < 2560) { Oh = Kh; Ol = Kl; hh = (col - 2048) >> 6; hcount = NG; dorope = true; }
                else                 { Oh = Vh; Ol = Vl; hh = (col - 2560) >> 6; hcount = NG; dorope = false; }
                const int pair = (col & 63) >> 1;
                float2 vv[2] = {v0, v1};
#pragma unroll
                for (int t = 0; t < 2; t++) {
                    const int r = row + t * 8;
                    const int bb = r >> 11, s = r & (SEQ - 1);
                    float x0 = vv[t].x, x1 = vv[t].y;
                    if (dorope) {
                        float2 cs = rope[s * 32 + pair];
                        float r0 = x0 * cs.x - x1 * cs.y;
                        x1 = x1 * cs.x + x0 * cs.y;
                        x0 = r0;
                    }
                    __nv_bfloat16 h0 = __float2bfloat16_rn(x0);
                    __nv_bfloat16 h1 = __float2bfloat16_rn(x1);
                    float l0f = x0 - __bfloat162float(h0);
                    float l1f = x1 - __bfloat162float(h1);
                    size_t o32 = ((size_t)(bb * hcount + hh) * SEQ + s) * 32 + pair;
                    reinterpret_cast<uint32_t*>(Oh)[o32] =
                        packbf(__bfloat162float(h0), __bfloat162float(h1));
                    reinterpret_cast<uint32_t*>(Ol)[o32] = packbf(l0f, l1f);
                }
            }
        }
    }
}

// ---------------------------------------------------------------------------
// Attention tile (unchanged from R12)
// ---------------------------------------------------------------------------
__device__ __forceinline__ void attn_tile(
    int a,
    const __nv_bfloat16* __restrict__ Qh, const __nv_bfloat16* __restrict__ Ql,
    const __nv_bfloat16* __restrict__ Kh, const __nv_bfloat16* __restrict__ Kl,
    const __nv_bfloat16* __restrict__ Vh, const __nv_bfloat16* __restrict__ Vl,
    __nv_bfloat16* __restrict__ Ch, __nv_bfloat16* __restrict__ Cl, char* smc)
{
    const uint32_t sb = smem_u32(smc);
    const int tid = threadIdx.x, lane = tid & 31, wid = tid >> 5;
    const int qt  = (SEQ / 128 - 1) - (a >> 6);
    const int sub = a & 63;
    const int h = sub >> 1, b = sub & 1;
    const int g = h >> 2;
    const int q0 = qt << 7;
    const int wrow = wid * 16;

    const size_t qbase = ((size_t)(b * NH + h) * SEQ + q0) * DH;
    const size_t kbase = ((size_t)(b * NG + g) * SEQ) * DH;

    constexpr uint32_t SQH = 0, SQL = 16384, SST = 32768, STAGE = 32768;

    const int fbase = b << 4;
    bool allM = true;
    {
        const volatile int* vf = (const volatile int*)g_flagM;
        for (int j = 0; j <= qt; j++) allM &= (vf[fbase + j] >= 24);
    }
    __threadfence();

    if (!allM) spin_ge(&g_flagM[fbase + qt], 24);
    {
#pragma unroll
        for (int i = 0; i < 4; i++) {
            int idx = tid + (i << 8);
            int r = idx >> 3, ch = idx & 7;
            uint32_t so = r * 128 + ((ch ^ (r & 7)) << 4);
            CP_ASYNC16(sb + SQH + so, Qh + qbase + r * 64 + ch * 8);
            CP_ASYNC16(sb + SQL + so, Ql + qbase + r * 64 + ch * 8);
        }
        CP_COMMIT();
    }
    auto fillkv = [&](int kt, int st) {
        const uint32_t s0 = sb + SST + st * STAGE;
        const size_t kb = kbase + (size_t)kt * 64 * 64;
#pragma unroll
        for (int i = 0; i < 2; i++) {
            int idx = tid + (i << 8);
            int r = idx >> 3, ch = idx & 7;
            uint32_t so = r * 128 + ((ch ^ (r & 7)) << 4);
            size_t go = kb + r * 64 + ch * 8;
            CP_ASYNC16(s0 +         so, Kh + go);
            CP_ASYNC16(s0 +  8192 + so, Kl + go);
            CP_ASYNC16(s0 + 16384 + so, Vh + go);
            CP_ASYNC16(s0 + 24576 + so, Vl + go);
        }
        CP_COMMIT();
    };
    const int nkt = (qt + 1) * 2;
    const int hi = nkt - 1;
    if (!allM) spin_ge(&g_flagM[fbase + (hi >> 1)], 24);
    fillkv(hi, hi & 1);
    if (hi >= 1) {
        if (!allM) spin_ge(&g_flagM[fbase + ((hi - 1) >> 1)], 24);
        fillkv(hi - 1, (hi - 1) & 1);
    } else CP_COMMIT();

    uint32_t qoff[4];
    {
        const int row = wrow + (lane & 7) + ((lane >> 3) & 1) * 8;
        const int chb = lane >> 4;
#pragma unroll
        for (int ks = 0; ks < 4; ks++)
            qoff[ks] = row * 128 + (((ks * 2 + chb) ^ (row & 7)) << 4);
    }

    float oac[8][4];
#pragma unroll
    for (int i = 0; i < 8; i++)
#pragma unroll
        for (int j = 0; j < 4; j++) oac[i][j] = 0.f;
    float ls0 = 0.f, ls1 = 0.f;
    const float slope8 = exp2f(-(float)(h + 1) * 0.25f) * 0.125f;
    const int qr = q0 + wrow + (lane >> 2);

    const int klrow = (lane & 7) + ((lane >> 4) << 3);
    const int klchb = (lane >> 3) & 1;
    const int vlrow = (lane & 7) + (((lane >> 3) & 1) << 3);
    const int vlchb = lane >> 4;

    for (int kt = hi; kt >= 0; kt--) {
        const int st = kt & 1;
        const uint32_t sK = sb + SST + st * STAGE;
        CP_WAIT1();
        __syncthreads();

        if ((kt << 6) <= q0 + wrow + 15) {
            float sc[8][4];
#pragma unroll
            for (int i = 0; i < 8; i++)
#pragma unroll
                for (int j = 0; j < 4; j++) sc[i][j] = 0.f;

#pragma unroll
            for (int ks = 0; ks < 4; ks++) {
                uint32_t qh_t[4], ql_t[4];
                ldsm4(qh_t, sb + SQH + qoff[ks]);
                ldsm4(ql_t, sb + SQL + qoff[ks]);
#pragma unroll
                for (int ng = 0; ng < 4; ng++) {
                    const int row = ng * 16 + klrow;
                    const uint32_t so = row * 128 + (((ks * 2 + klchb) ^ (row & 7)) << 4);
                    uint32_t kfh[4], kfl[4];
                    ldsm4(kfh, sK + so);
                    ldsm4(kfl, sK + 8192 + so);
                    mma16816(sc[ng * 2],     qh_t, kfh);
                    mma16816(sc[ng * 2],     qh_t, kfl);
                    mma16816(sc[ng * 2],     ql_t, kfh);
                    mma16816(sc[ng * 2 + 1], qh_t, kfh + 2);
                    mma16816(sc[ng * 2 + 1], qh_t, kfl + 2);
                    mma16816(sc[ng * 2 + 1], ql_t, kfh + 2);
                }
            }

            const int kcol0 = (kt << 6) + (lane & 3) * 2;
            const bool tail = ((kt << 6) + 63 > q0 + wrow);
#pragma unroll
            for (int nf = 0; nf < 8; nf++) {
                const int kc = kcol0 + nf * 8;
                const float bias0 = slope8 * (float)(kc - qr);
                float p0 = softmax_p(fmaf(sc[nf][0], 0.125f, bias0));
                float p1 = softmax_p(fmaf(sc[nf][1], 0.125f, bias0 + slope8));
                float p2 = softmax_p(fmaf(sc[nf][2], 0.125f, bias0 - 8.f * slope8));
                float p3 = softmax_p(fmaf(sc[nf][3], 0.125f, bias0 - 7.f * slope8));
                if (tail) {
                    if (kc > qr)         p0 = 0.f;
                    if (kc + 1 > qr)     p1 = 0.f;
                    if (kc > qr + 8)     p2 = 0.f;
                    if (kc + 1 > qr + 8) p3 = 0.f;
                }
                ls0 += p0 + p1;
                ls1 += p2 + p3;
                sc[nf][0] = p0; sc[nf][1] = p1; sc[nf][2] = p2; sc[nf][3] = p3;
            }

#pragma unroll
            for (int j = 0; j < 4; j++) {
                uint32_t pah[4], pal[4];
#pragma unroll
                for (int u = 0; u < 2; u++) {
                    const float* p = sc[2 * j + u];
                    split_pair(p[0], p[1], pah[2 * u],     pal[2 * u]);
                    split_pair(p[2], p[3], pah[2 * u + 1], pal[2 * u + 1]);
                }
#pragma unroll
                for (int gD = 0; gD < 4; gD++) {
                    const int row = j * 16 + vlrow;
                    const uint32_t so = row * 128 + (((gD * 2 + vlchb) ^ (row & 7)) << 4);
                    uint32_t vfh[4], vfl[4];
                    ldsm4t(vfh, sK + 16384 + so);
                    ldsm4t(vfl, sK + 24576 + so);
                    mma16816(oac[gD * 2],     pah, vfh);
                    mma16816(oac[gD * 2],     pah, vfl);
                    mma16816(oac[gD * 2],     pal, vfh);
                    mma16816(oac[gD * 2 + 1], pah, vfh + 2);
                    mma16816(oac[gD * 2 + 1], pah, vfl + 2);
                    mma16816(oac[gD * 2 + 1], pal, vfh + 2);
                }
            }
        }
        __syncthreads();
        if (kt - 2 >= 0) {
            if (!allM) spin_ge(&g_flagM[fbase + ((kt - 2) >> 1)], 24);
            fillkv(kt - 2, st);
        } else CP_COMMIT();
    }

    ls0 += __shfl_xor_sync(0xffffffffu, ls0, 1);
    ls0 += __shfl_xor_sync(0xffffffffu, ls0, 2);
    ls1 += __shfl_xor_sync(0xffffffffu, ls1, 1);
    ls1 += __shfl_xor_sync(0xffffffffu, ls1, 2);
    const float inv0 = 1.f / ls0, inv1 = 1.f / ls1;

    const size_t rowM0 = (size_t)b * SEQ + qr;
#pragma unroll
    for (int nf = 0; nf < 8; nf++) {
        const int col = h * 64 + nf * 8 + (lane & 3) * 2;
        float x0 = oac[nf][0] * inv0, x1 = oac[nf][1] * inv0;
        float y0 = oac[nf][2] * inv1, y1 = oac[nf][3] * inv1;
        __nv_bfloat16 hx0 = __float2bfloat16_rn(x0), hx1 = __float2bfloat16_rn(x1);
        __nv_bfloat16 hy0 = __float2bfloat16_rn(y0), hy1 = __float2bfloat16_rn(y1);
        size_t o0 = (rowM0 * DM + col) >> 1;
        size_t o1 = ((rowM0 + 8) * DM + col) >> 1;
        reinterpret_cast<uint32_t*>(Ch)[o0] = packbf(__bfloat162float(hx0), __bfloat162float(hx1));
        reinterpret_cast<uint32_t*>(Cl)[o0] = packbf(x0 - __bfloat162float(hx0), x1 - __bfloat162float(hx1));
        reinterpret_cast<uint32_t*>(Ch)[o1] = packbf(__bfloat162float(hy0), __bfloat162float(hy1));
        reinterpret_cast<uint32_t*>(Cl)[o1] = packbf(y0 - __bfloat162float(hy0), y1 - __bfloat162float(hy1));
    }
    __threadfence();
    __syncthreads();
    if (tid == 0) atomicAdd(&g_flagA[fbase + qt], 1);
}

// ---------------------------------------------------------------------------
// Transpose+split a 128x128 slice of W [K,N] into T [N-major, DM cols].
// Uses dynamic smem as a 32x33 float staging tile.
// ---------------------------------------------------------------------------
__device__ __forceinline__ void transpose_slice(
    const float* __restrict__ W, int N, int n0, int k0, int rowoff,
    __nv_bfloat16* __restrict__ Th, __nv_bfloat16* __restrict__ Tl, char* smc)
{
    float* t = reinterpret_cast<float*>(smc);
    const int tid = threadIdx.x;
    const int tx = tid & 31, ty = tid >> 5;    // 32 x 8
    for (int st = 0; st < 16; st++) {
        const int kk = k0 + ((st >> 2) << 5), nn = n0 + ((st & 3) << 5);
        __syncthreads();
#pragma unroll
        for (int i = 0; i < 4; i++)
            t[(ty + 8 * i) * 33 + tx] = W[(size_t)(kk + ty + 8 * i) * N + nn + tx];
        __syncthreads();
#pragma unroll
        for (int i = 0; i < 4; i++) {
            float v = t[tx * 33 + ty + 8 * i];
            __nv_bfloat16 h = __float2bfloat16_rn(v);
            __nv_bfloat16 l = __float2bfloat16_rn(v - __bfloat162float(h));
            size_t o = (size_t)(rowoff + nn + ty + 8 * i) * DM + kk + tx;
            Th[o] = h; Tl[o] = l;
        }
    }
}

// ---------------------------------------------------------------------------
// ONE fused launch: prep (flagged) -> QKV gemm -> attention -> out-proj.
// Self-cleaning flags for graph replay.
// ---------------------------------------------------------------------------
__global__ __launch_bounds__(256, 2)
void fused_all(const float* __restrict__ hs,
               const float* __restrict__ Wq, const float* __restrict__ Wk,
               const float* __restrict__ Wv, const float* __restrict__ Wo,
               const float* __restrict__ bo, float* __restrict__ out)
{
    extern __shared__ __align__(128) char smc[];
    const int bid = blockIdx.x;
    const int tid = threadIdx.x;

    if (bid < B_WO) {
        // Wqkv transpose slice: cb (0..23) x ks (0..15)
        const int cb = bid >> 4, ks = bid & 15;
        const float* W; int N, rowoff, nb;
        if (cb < 16)      { W = Wq; N = 2048; rowoff = 0;    nb = cb; }
        else if (cb < 20) { W = Wk; N = 512;  rowoff = 2048; nb = cb - 16; }
        else              { W = Wv; N = 512;  rowoff = 2560; nb = cb - 20; }
        transpose_slice(W, N, nb << 7, ks << 7, rowoff, g_wch, g_wcl, smc);
        __threadfence();
        __syncthreads();
        if (tid == 0) atomicAdd(&g_flagW[cb], 1);
    } else if (bid < B_ASP) {
        // Wo transpose slice: nb (0..15) x ks (0..15)
        const int o = bid - B_WO;
        const int nb = o >> 4, ks = o & 15;
        transpose_slice(Wo, 2048, nb << 7, ks << 7, 0, g_woh, g_wol, smc);
        __threadfence();
        __syncthreads();
        if (tid == 0) atomicAdd(&g_flagWo[nb], 1);
    } else if (bid < B_ROPE) {
        // hs split slice: rb (0..31) x ks (0..15): rows rb*128..+128, cols ks*128..+128
        const int o = bid - B_ASP;
        const int rb = o >> 4, ks = o & 15;
        const size_t base = (size_t)(rb << 7) * 512 + (ks << 5);   // float4 units
#pragma unroll
        for (int u = 0; u < 16; u++) {
            int e = u * 256 + tid;
            int r = e >> 5, c = e & 31;
            size_t i = base + (size_t)r * 512 + c;
            float4 v = reinterpret_cast<const float4*>(hs)[i];
            float f[4] = {v.x, v.y, v.z, v.w};
            __nv_bfloat16 hh[4], ll[4];
#pragma unroll
            for (int j = 0; j < 4; j++) {
                hh[j] = __float2bfloat16_rn(f[j]);
                ll[j] = __float2bfloat16_rn(f[j] - __bfloat162float(hh[j]));
            }
            reinterpret_cast<uint2*>(g_ah)[i] = *reinterpret_cast<uint2*>(hh);
            reinterpret_cast<uint2*>(g_al)[i] = *reinterpret_cast<uint2*>(ll);
        }
        __threadfence();
        __syncthreads();
        if (tid == 0) atomicAdd(&g_flagAsp[rb], 1);
    } else if (bid < B_QKV) {
        // rope table slice: 8 CTAs x 8192 entries
        const int ct = bid - B_ROPE;
#pragma unroll
        for (int u = 0; u < 32; u++) {
            int id = ct * 8192 + u * 256 + tid;
            int s = id >> 5, pair = id & 31;
            float inv = powf(10000.f, -(float)(2 * pair) * (1.f / 64.f));
            float sn, c;
            sincosf((float)s * inv, &sn, &c);
            g_rope[id] = make_float2(c, sn);
        }
        __threadfence();
        __syncthreads();
        if (tid == 0) atomicAdd(&g_flagR, 1);
    } else if (bid < B_ATT) {
        // QKV gemm tile
        const int q = bid - B_QKV;
        const int nt = q % 24, y = q / 24;
        const int sblk = 15 - (y >> 1), bq = y & 1;
        const int mblk = (bq << 4) + sblk;
        spin_ge(&g_flagAsp[mblk], 16);
        spin_ge(&g_flagW[nt], 16);
        spin_ge(&g_flagR, 8);
        gemm_tile(g_ah, g_al, g_wch, g_wcl, nullptr,
                  g_qh, g_ql, g_kh, g_kl, g_vh, g_vl, g_rope,
                  NQKV, 3, nullptr, mblk << 7, nt << 7, smc);
        __threadfence();
        __syncthreads();
        if (tid == 0) atomicAdd(&g_flagM[mblk], 1);
    } else if (bid < B_OUT) {
        attn_tile(bid - B_ATT, g_qh, g_ql, g_kh, g_kl, g_vh, g_vl, g_ah, g_al, smc);
    } else {
        // out-proj tile
        const int o = bid - B_OUT;
        const int mi = o >> 4, nb = o & 15;
        const int qtm = 15 - (mi >> 1), bm = mi & 1;
        const int mblk = (bm << 4) + qtm;
        spin_ge(&g_flagWo[nb], 16);
        spin_ge(&g_flagA[mblk], 32);
        gemm_tile(g_ah, g_al, g_woh, g_wol, out,
                  nullptr, nullptr, nullptr, nullptr, nullptr, nullptr, nullptr,
                  DM, 0, bo, mblk << 7, nb << 7, smc);
        // self-cleaning: last out-proj CTA resets all flags for graph replay
        __syncthreads();
        if (tid == 0) {
            int d = atomicAdd(&g_done, 1);
            if (d == 511) {
#pragma unroll
                for (int i = 0; i < 32; i++) { g_flagM[i] = 0; g_flagA[i] = 0; g_flagAsp[i] = 0; }
#pragma unroll
                for (int i = 0; i < 24; i++) g_flagW[i] = 0;
#pragma unroll
                for (int i = 0; i < 16; i++) g_flagWo[i] = 0;
                g_flagR = 0;
                g_done = 0;
                __threadfence();
            }
        }
    }
}

// ---------------------------------------------------------------------------
extern "C" void kernel_launch(void* const* d_in, const int* in_sizes, int n_in,
                              void* d_out, int out_size)
{
    const float* hs = (const float*)d_in[0];
    const float* Wq = (const float*)d_in[1];
    const float* Wk = (const float*)d_in[2];
    const float* Wv = (const float*)d_in[3];
    const float* Wo = (const float*)d_in[4];
    const float* bo = (const float*)d_in[5];
    float* out = (float*)d_out;

    const int mega_smem = 3 * 32768;   // 96 KB
    cudaFuncSetAttribute(fused_all, cudaFuncAttributeMaxDynamicSharedMemorySize, mega_smem);

    // single fused launch: prep + QKV gemm + attention + out-proj
    fused_all<<<dim3(B_TOTAL), 256, mega_smem>>>(hs, Wq, Wk, Wv, Wo, bo, out);
}

// round 15
// speedup vs baseline: 1.0958x; 1.0958x over previous
#include <cuda_runtime.h>
#include <cuda_bf16.h>
#include <cuda_fp16.h>
#include <math.h>
#include <stdint.h>

#define DM    2048
#define SEQ   2048
#define BATCH 2
#define NH    32
#define NG    8
#define DH    64
#define MROWS (BATCH*SEQ)   // 4096
#define NQKV  3072

// ---------------- scratch (__device__ globals; no allocs allowed) ----------
__device__ __nv_bfloat16 g_ah[(size_t)MROWS*DM];   // A split (hs, later ctx)
__device__ __nv_bfloat16 g_al[(size_t)MROWS*DM];
__device__ __nv_bfloat16 g_wch[(size_t)NQKV*DM], g_wcl[(size_t)NQKV*DM];
__device__ __nv_bfloat16 g_woh[(size_t)DM*DM],   g_wol[(size_t)DM*DM];
__device__ __half g_qh[(size_t)BATCH*NH*SEQ*DH], g_ql[(size_t)BATCH*NH*SEQ*DH];
__device__ __half g_kh[(size_t)BATCH*NG*SEQ*DH];
__device__ __half g_vh[(size_t)BATCH*NG*SEQ*DH], g_vl[(size_t)BATCH*NG*SEQ*DH];
__device__ float2 g_rope[SEQ * 32];
__device__ int g_flagM[32];   // per 128-row block: QKV N-tile arrivals (target 24)
__device__ int g_flagA[32];   // per 128-row block: attention head arrivals (target 32)

// ---------------- helpers ---------------------------------------------------
__device__ __forceinline__ uint32_t smem_u32(const void* p) {
    uint32_t a;
    asm("{ .reg .u64 t; cvta.to.shared.u64 t, %1; cvt.u32.u64 %0, t; }" : "=r"(a) : "l"(p));
    return a;
}
__device__ __forceinline__ void ldsm4(uint32_t* r, uint32_t addr) {
    asm volatile("ldmatrix.sync.aligned.m8n8.x4.shared.b16 {%0,%1,%2,%3}, [%4];"
                 : "=r"(r[0]), "=r"(r[1]), "=r"(r[2]), "=r"(r[3]) : "r"(addr));
}
__device__ __forceinline__ void ldsm4t(uint32_t* r, uint32_t addr) {
    asm volatile("ldmatrix.sync.aligned.m8n8.x4.trans.shared.b16 {%0,%1,%2,%3}, [%4];"
                 : "=r"(r[0]), "=r"(r[1]), "=r"(r[2]), "=r"(r[3]) : "r"(addr));
}
__device__ __forceinline__ void mma16816(float* c, const uint32_t* a, const uint32_t* b) {
    asm volatile("mma.sync.aligned.m16n8k16.row.col.f32.bf16.bf16.f32 "
                 "{%0,%1,%2,%3}, {%4,%5,%6,%7}, {%8,%9}, {%0,%1,%2,%3};"
                 : "+f"(c[0]), "+f"(c[1]), "+f"(c[2]), "+f"(c[3])
                 : "r"(a[0]), "r"(a[1]), "r"(a[2]), "r"(a[3]), "r"(b[0]), "r"(b[1]));
}
__device__ __forceinline__ void mma16816h(float* c, const uint32_t* a, const uint32_t* b) {
    asm volatile("mma.sync.aligned.m16n8k16.row.col.f32.f16.f16.f32 "
                 "{%0,%1,%2,%3}, {%4,%5,%6,%7}, {%8,%9}, {%0,%1,%2,%3};"
                 : "+f"(c[0]), "+f"(c[1]), "+f"(c[2]), "+f"(c[3])
                 : "r"(a[0]), "r"(a[1]), "r"(a[2]), "r"(a[3]), "r"(b[0]), "r"(b[1]));
}
#define CP_ASYNC16(s, g) \
    asm volatile("cp.async.cg.shared.global [%0], [%1], 16;" :: "r"(s), "l"(g))
#define CP_COMMIT() asm volatile("cp.async.commit_group;" ::: "memory")
#define CP_WAIT1()  asm volatile("cp.async.wait_group 1;" ::: "memory")

__device__ __forceinline__ uint32_t packbf(float lo, float hi) {
    __nv_bfloat162 t = __floats2bfloat162_rn(lo, hi);
    return *reinterpret_cast<uint32_t*>(&t);
}
__device__ __forceinline__ uint32_t packh(float lo, float hi) {
    __half2 t = __floats2half2_rn(lo, hi);
    return *reinterpret_cast<uint32_t*>(&t);
}
__device__ __forceinline__ float ex2f(float x) {
    float r;
    asm("ex2.approx.ftz.f32 %0, %1;" : "=f"(r) : "f"(x));
    return r;
}
// p' = 2^40 * exp(30*tanh(s/30) - 30)  (scaled so fp16 P doesn't underflow;
// the 2^40 cancels in oac/ls since both use the same scaled values).
__device__ __forceinline__ float softmax_p(float sv) {
    const float s2 = sv * sv;
    const float P = fmaf(s2, fmaf(s2, 2.3748002e-7f, -5.3433150e-4f), 1.44269504f);
    return ex2f(fmaf(sv, P, -3.2808512f));
}
__device__ __forceinline__ void spin_ge(const int* f, int target) {
    const volatile int* vf = (const volatile int*)f;
    while (*vf < target) __nanosleep(128);
    __threadfence();
}

// ---------------------------------------------------------------------------
// bf16x3 HMMA GEMM tile: 128x128 CTA tile, BK=32, 3-stage cp.async ring.
// mode 0: fp32 row-major + bias.
// mode 3: combined QKV epilogue -> Q fp16 hi/lo (rope), K fp16 (rope), V fp16 hi/lo.
// ---------------------------------------------------------------------------
__device__ __forceinline__ void gemm_tile(
    const __nv_bfloat16* __restrict__ Ah, const __nv_bfloat16* __restrict__ Al,
    const __nv_bfloat16* __restrict__ Bh, const __nv_bfloat16* __restrict__ Bl,
    float* __restrict__ Cf,
    __half* __restrict__ Qh, __half* __restrict__ Ql,
    __half* __restrict__ Kh,
    __half* __restrict__ Vh, __half* __restrict__ Vl,
    const float2* __restrict__ rope,
    int Ntot, int mode, const float* __restrict__ bias,
    int m0, int n0, char* smc)
{
    const uint32_t sbase = smem_u32(smc);
    const int tid = threadIdx.x, lane = tid & 31, wid = tid >> 5;
    const int wm = wid >> 2, wn = wid & 3;
    const int fr = tid >> 2;
    const int fc = tid & 3;

    uint32_t offA[4][2], offB[2][2];
#pragma unroll
    for (int mf = 0; mf < 4; mf++)
#pragma unroll
        for (int ks = 0; ks < 2; ks++) {
            int row = wm * 64 + mf * 16 + (lane & 7) + ((lane >> 3) & 1) * 8;
            int ch  = ks * 2 + (lane >> 4);
            offA[mf][ks] = row * 64 + ((ch ^ ((row >> 1) & 3)) << 4);
        }
#pragma unroll
    for (int np = 0; np < 2; np++)
#pragma unroll
        for (int ks = 0; ks < 2; ks++) {
            int row = wn * 32 + np * 16 + (lane & 7) + (lane >> 4) * 8;
            int ch  = ks * 2 + ((lane >> 3) & 1);
            offB[np][ks] = row * 64 + ((ch ^ ((row >> 1) & 3)) << 4);
        }

    float acc[4][4][4];
#pragma unroll
    for (int i = 0; i < 4; i++)
#pragma unroll
        for (int j = 0; j < 4; j++)
#pragma unroll
            for (int l = 0; l < 4; l++) acc[i][j][l] = 0.f;

    auto fill = [&](int kc, int stage) {
        const uint32_t sb = sbase + stage * 32768;
#pragma unroll
        for (int i = 0; i < 2; i++) {
            const int r = fr + i * 64;
            const uint32_t so = r * 64 + ((fc ^ ((r >> 1) & 3)) << 4);
            const size_t gA = (size_t)(m0 + r) * DM + kc * 32 + fc * 8;
            const size_t gB = (size_t)(n0 + r) * DM + kc * 32 + fc * 8;
            CP_ASYNC16(sb +         so, Ah + gA);
            CP_ASYNC16(sb +  8192 + so, Al + gA);
            CP_ASYNC16(sb + 16384 + so, Bh + gB);
            CP_ASYNC16(sb + 24576 + so, Bl + gB);
        }
        CP_COMMIT();
    };

    fill(0, 0);
    fill(1, 1);

    const int NKC = DM / 32;
    int rd = 0, wr = 2;
    for (int kc = 0; kc < NKC; kc++) {
        CP_WAIT1();
        __syncthreads();
        const uint32_t sA = sbase + rd * 32768;
#pragma unroll
        for (int ks = 0; ks < 2; ks++) {
            uint32_t bh[2][4], bl[2][4];
#pragma unroll
            for (int np = 0; np < 2; np++) {
                ldsm4(bh[np], sA + 16384 + offB[np][ks]);
                ldsm4(bl[np], sA + 24576 + offB[np][ks]);
            }
#pragma unroll
            for (int mf = 0; mf < 4; mf++) {
                uint32_t ah[4], al[4];
                ldsm4(ah, sA +        offA[mf][ks]);
                ldsm4(al, sA + 8192 + offA[mf][ks]);
#pragma unroll
                for (int nf = 0; nf < 4; nf++) {
                    const uint32_t* bhp = &bh[nf >> 1][(nf & 1) * 2];
                    const uint32_t* blp = &bl[nf >> 1][(nf & 1) * 2];
                    mma16816(acc[mf][nf], ah, bhp);
                    mma16816(acc[mf][nf], ah, blp);
                    mma16816(acc[mf][nf], al, bhp);
                }
            }
        }
        if (kc + 2 < NKC) fill(kc + 2, wr);
        else CP_COMMIT();
        rd = (rd == 2) ? 0 : rd + 1;
        wr = (wr == 2) ? 0 : wr + 1;
    }

    const int g4 = lane >> 2, t4 = lane & 3;
#pragma unroll
    for (int mf = 0; mf < 4; mf++) {
#pragma unroll
        for (int nf = 0; nf < 4; nf++) {
            const int row = m0 + wm * 64 + mf * 16 + g4;
            const int col = n0 + wn * 32 + nf * 8 + t4 * 2;
            float2 v0 = make_float2(acc[mf][nf][0], acc[mf][nf][1]);
            float2 v1 = make_float2(acc[mf][nf][2], acc[mf][nf][3]);
            if (mode == 0) {
                const float b0 = bias[col], b1 = bias[col + 1];
                v0.x += b0; v0.y += b1; v1.x += b0; v1.y += b1;
                *reinterpret_cast<float2*>(Cf + (size_t)row * Ntot + col)       = v0;
                *reinterpret_cast<float2*>(Cf + (size_t)(row + 8) * Ntot + col) = v1;
            } else {
                const int pair = (col & 63) >> 1;
                float2 vv[2] = {v0, v1};
#pragma unroll
                for (int t = 0; t < 2; t++) {
                    const int r = row + t * 8;
                    const int bb = r >> 11, s = r & (SEQ - 1);
                    float x0 = vv[t].x, x1 = vv[t].y;
                    if (col < 2560) {
                        float2 cs = rope[s * 32 + pair];
                        float r0 = x0 * cs.x - x1 * cs.y;
                        x1 = x1 * cs.x + x0 * cs.y;
                        x0 = r0;
                    }
                    if (col < 2048) {        // Q: fp16 hi/lo
                        const int hh = col >> 6;
                        size_t o32 = ((size_t)(bb * NH + hh) * SEQ + s) * 32 + pair;
                        __half h0 = __float2half_rn(x0), h1 = __float2half_rn(x1);
                        __half2 hp = __halves2half2(h0, h1);
                        reinterpret_cast<uint32_t*>(Qh)[o32] = *reinterpret_cast<uint32_t*>(&hp);
                        reinterpret_cast<uint32_t*>(Ql)[o32] =
                            packh(x0 - __half2float(h0), x1 - __half2float(h1));
                    } else if (col < 2560) { // K: fp16 single
                        const int hh = (col - 2048) >> 6;
                        size_t o32 = ((size_t)(bb * NG + hh) * SEQ + s) * 32 + pair;
                        reinterpret_cast<uint32_t*>(Kh)[o32] = packh(x0, x1);
                    } else {                 // V: fp16 hi/lo
                        const int hh = (col - 2560) >> 6;
                        size_t o32 = ((size_t)(bb * NG + hh) * SEQ + s) * 32 + pair;
                        __half h0 = __float2half_rn(x0), h1 = __float2half_rn(x1);
                        __half2 hp = __halves2half2(h0, h1);
                        reinterpret_cast<uint32_t*>(Vh)[o32] = *reinterpret_cast<uint32_t*>(&hp);
                        reinterpret_cast<uint32_t*>(Vl)[o32] =
                            packh(x0 - __half2float(h0), x1 - __half2float(h1));
                    }
                }
            }
        }
    }
}

// ---------------------------------------------------------------------------
// Attention tile: fp16 path. S = (Qh+Ql)*K (2 MMAs), O = P*(Vh+Vl) (2 MMAs).
// P scaled by 2^40 before fp16 conversion (cancels in O/ls).
// ---------------------------------------------------------------------------
__device__ __forceinline__ void attn_tile(
    int a,
    const __half* __restrict__ Qh, const __half* __restrict__ Ql,
    const __half* __restrict__ Kh,
    const __half* __restrict__ Vh, const __half* __restrict__ Vl,
    __nv_bfloat16* __restrict__ Ch, __nv_bfloat16* __restrict__ Cl, char* smc)
{
    const uint32_t sb = smem_u32(smc);
    const int tid = threadIdx.x, lane = tid & 31, wid = tid >> 5;
    const int qt  = (SEQ / 128 - 1) - (a >> 6);
    const int sub = a & 63;
    const int h = sub >> 1, b = sub & 1;
    const int g = h >> 2;
    const int q0 = qt << 7;
    const int wrow = wid * 16;

    const size_t qbase = ((size_t)(b * NH + h) * SEQ + q0) * DH;
    const size_t kbase = ((size_t)(b * NG + g) * SEQ) * DH;

    constexpr uint32_t SQH = 0, SQL = 16384, SST = 32768, STAGE = 24576;

    const int fbase = b << 4;
    bool allM = true;
    {
        const volatile int* vf = (const volatile int*)g_flagM;
        for (int j = 0; j <= qt; j++) allM &= (vf[fbase + j] >= 24);
    }
    __threadfence();

    if (!allM) spin_ge(&g_flagM[fbase + qt], 24);
    {
#pragma unroll
        for (int i = 0; i < 4; i++) {
            int idx = tid + (i << 8);
            int r = idx >> 3, ch = idx & 7;
            uint32_t so = r * 128 + ((ch ^ (r & 7)) << 4);
            CP_ASYNC16(sb + SQH + so, Qh + qbase + r * 64 + ch * 8);
            CP_ASYNC16(sb + SQL + so, Ql + qbase + r * 64 + ch * 8);
        }
        CP_COMMIT();
    }
    auto fillkv = [&](int kt, int st) {
        const uint32_t s0 = sb + SST + st * STAGE;
        const size_t kb = kbase + (size_t)kt * 64 * 64;
#pragma unroll
        for (int i = 0; i < 2; i++) {
            int idx = tid + (i << 8);
            int r = idx >> 3, ch = idx & 7;
            uint32_t so = r * 128 + ((ch ^ (r & 7)) << 4);
            size_t go = kb + r * 64 + ch * 8;
            CP_ASYNC16(s0 +         so, Kh + go);
            CP_ASYNC16(s0 +  8192 + so, Vh + go);
            CP_ASYNC16(s0 + 16384 + so, Vl + go);
        }
        CP_COMMIT();
    };
    const int nkt = (qt + 1) * 2;
    const int hi = nkt - 1;
    if (!allM) spin_ge(&g_flagM[fbase + (hi >> 1)], 24);
    fillkv(hi, hi & 1);
    if (hi >= 1) {
        if (!allM) spin_ge(&g_flagM[fbase + ((hi - 1) >> 1)], 24);
        fillkv(hi - 1, (hi - 1) & 1);
    } else CP_COMMIT();

    uint32_t qoff[4];
    {
        const int row = wrow + (lane & 7) + ((lane >> 3) & 1) * 8;
        const int chb = lane >> 4;
#pragma unroll
        for (int ks = 0; ks < 4; ks++)
            qoff[ks] = row * 128 + (((ks * 2 + chb) ^ (row & 7)) << 4);
    }

    float oac[8][4];
#pragma unroll
    for (int i = 0; i < 8; i++)
#pragma unroll
        for (int j = 0; j < 4; j++) oac[i][j] = 0.f;
    float ls0 = 0.f, ls1 = 0.f;
    const float slope8 = exp2f(-(float)(h + 1) * 0.25f) * 0.125f;
    const int qr = q0 + wrow + (lane >> 2);

    const int klrow = (lane & 7) + ((lane >> 4) << 3);
    const int klchb = (lane >> 3) & 1;
    const int vlrow = (lane & 7) + (((lane >> 3) & 1) << 3);
    const int vlchb = lane >> 4;

    for (int kt = hi; kt >= 0; kt--) {
        const int st = kt & 1;
        const uint32_t sK = sb + SST + st * STAGE;
        CP_WAIT1();
        __syncthreads();

        if ((kt << 6) <= q0 + wrow + 15) {
            float sc[8][4];
#pragma unroll
            for (int i = 0; i < 8; i++)
#pragma unroll
                for (int j = 0; j < 4; j++) sc[i][j] = 0.f;

#pragma unroll
            for (int ks = 0; ks < 4; ks++) {
                uint32_t qh_t[4], ql_t[4];
                ldsm4(qh_t, sb + SQH + qoff[ks]);
                ldsm4(ql_t, sb + SQL + qoff[ks]);
#pragma unroll
                for (int ng = 0; ng < 4; ng++) {
                    const int row = ng * 16 + klrow;
                    const uint32_t so = row * 128 + (((ks * 2 + klchb) ^ (row & 7)) << 4);
                    uint32_t kf[4];
                    ldsm4(kf, sK + so);
                    mma16816h(sc[ng * 2],     qh_t, kf);
                    mma16816h(sc[ng * 2],     ql_t, kf);
                    mma16816h(sc[ng * 2 + 1], qh_t, kf + 2);
                    mma16816h(sc[ng * 2 + 1], ql_t, kf + 2);
                }
            }

            const int kcol0 = (kt << 6) + (lane & 3) * 2;
            const bool tail = ((kt << 6) + 63 > q0 + wrow);
#pragma unroll
            for (int nf = 0; nf < 8; nf++) {
                const int kc = kcol0 + nf * 8;
                const float bias0 = slope8 * (float)(kc - qr);
                float p0 = softmax_p(fmaf(sc[nf][0], 0.125f, bias0));
                float p1 = softmax_p(fmaf(sc[nf][1], 0.125f, bias0 + slope8));
                float p2 = softmax_p(fmaf(sc[nf][2], 0.125f, bias0 - 8.f * slope8));
                float p3 = softmax_p(fmaf(sc[nf][3], 0.125f, bias0 - 7.f * slope8));
                if (tail) {
                    if (kc > qr)         p0 = 0.f;
                    if (kc + 1 > qr)     p1 = 0.f;
                    if (kc > qr + 8)     p2 = 0.f;
                    if (kc + 1 > qr + 8) p3 = 0.f;
                }
                ls0 += p0 + p1;
                ls1 += p2 + p3;
                sc[nf][0] = p0; sc[nf][1] = p1; sc[nf][2] = p2; sc[nf][3] = p3;
            }

#pragma unroll
            for (int j = 0; j < 4; j++) {
                uint32_t pa[4];
                pa[0] = packh(sc[2 * j][0],     sc[2 * j][1]);
                pa[1] = packh(sc[2 * j][2],     sc[2 * j][3]);
                pa[2] = packh(sc[2 * j + 1][0], sc[2 * j + 1][1]);
                pa[3] = packh(sc[2 * j + 1][2], sc[2 * j + 1][3]);
#pragma unroll
                for (int gD = 0; gD < 4; gD++) {
                    const int row = j * 16 + vlrow;
                    const uint32_t so = row * 128 + (((gD * 2 + vlchb) ^ (row & 7)) << 4);
                    uint32_t vfh[4], vfl[4];
                    ldsm4t(vfh, sK +  8192 + so);
                    ldsm4t(vfl, sK + 16384 + so);
                    mma16816h(oac[gD * 2],     pa, vfh);
                    mma16816h(oac[gD * 2],     pa, vfl);
                    mma16816h(oac[gD * 2 + 1], pa, vfh + 2);
                    mma16816h(oac[gD * 2 + 1], pa, vfl + 2);
                }
            }
        }
        __syncthreads();
        if (kt - 2 >= 0) {
            if (!allM) spin_ge(&g_flagM[fbase + ((kt - 2) >> 1)], 24);
            fillkv(kt - 2, st);
        } else CP_COMMIT();
    }

    ls0 += __shfl_xor_sync(0xffffffffu, ls0, 1);
    ls0 += __shfl_xor_sync(0xffffffffu, ls0, 2);
    ls1 += __shfl_xor_sync(0xffffffffu, ls1, 1);
    ls1 += __shfl_xor_sync(0xffffffffu, ls1, 2);
    const float inv0 = 1.f / ls0, inv1 = 1.f / ls1;

    const size_t rowM0 = (size_t)b * SEQ + qr;
#pragma unroll
    for (int nf = 0; nf < 8; nf++) {
        const int col = h * 64 + nf * 8 + (lane & 3) * 2;
        float x0 = oac[nf][0] * inv0, x1 = oac[nf][1] * inv0;
        float y0 = oac[nf][2] * inv1, y1 = oac[nf][3] * inv1;
        __nv_bfloat16 hx0 = __float2bfloat16_rn(x0), hx1 = __float2bfloat16_rn(x1);
        __nv_bfloat16 hy0 = __float2bfloat16_rn(y0), hy1 = __float2bfloat16_rn(y1);
        size_t o0 = (rowM0 * DM + col) >> 1;
        size_t o1 = ((rowM0 + 8) * DM + col) >> 1;
        reinterpret_cast<uint32_t*>(Ch)[o0] = packbf(__bfloat162float(hx0), __bfloat162float(hx1));
        reinterpret_cast<uint32_t*>(Cl)[o0] = packbf(x0 - __bfloat162float(hx0), x1 - __bfloat162float(hx1));
        reinterpret_cast<uint32_t*>(Ch)[o1] = packbf(__bfloat162float(hy0), __bfloat162float(hy1));
        reinterpret_cast<uint32_t*>(Cl)[o1] = packbf(y0 - __bfloat162float(hy0), y1 - __bfloat162float(hy1));
    }
    __threadfence();
    __syncthreads();
    if (tid == 0) atomicAdd(&g_flagA[fbase + qt], 1);
}

// ---------------------------------------------------------------------------
// Fused mega-kernel: QKV gemm tiles -> attention -> out-proj, flag-synced.
// ---------------------------------------------------------------------------
__global__ __launch_bounds__(256, 2)
void fused_mega(const float* __restrict__ bo, float* __restrict__ out)
{
    extern __shared__ __align__(128) char smc[];
    const int bid = blockIdx.x;

    if (bid < 768) {
        const int nt = bid % 24, y = bid / 24;
        const int sblk = 15 - (y >> 1), bq = y & 1;
        const int m0 = ((bq << 4) + sblk) << 7;
        gemm_tile(g_ah, g_al, g_wch, g_wcl, nullptr,
                  g_qh, g_ql, g_kh, g_vh, g_vl, g_rope,
                  NQKV, 3, nullptr, m0, nt << 7, smc);
        __threadfence();
        __syncthreads();
        if (threadIdx.x == 0) atomicAdd(&g_flagM[m0 >> 7], 1);
    } else if (bid < 1792) {
        attn_tile(bid - 768, g_qh, g_ql, g_kh, g_vh, g_vl, g_ah, g_al, smc);
    } else {
        const int o = bid - 1792;
        const int mi = o >> 4, nb = o & 15;
        const int qtm = 15 - (mi >> 1), bm = mi & 1;
        const int m0 = ((bm << 4) + qtm) << 7;
        spin_ge(&g_flagA[m0 >> 7], 32);
        gemm_tile(g_ah, g_al, g_woh, g_wol, out,
                  nullptr, nullptr, nullptr, nullptr, nullptr, nullptr,
                  DM, 0, bo, m0, nb << 7, smc);
    }
}

// ---------------------------------------------------------------------------
// ONE prep launch: weight transposes + hs split + rope table + flag zeroing.
// ---------------------------------------------------------------------------
__global__ void prep_all(const float* __restrict__ hs,
                         const float* __restrict__ Wq, const float* __restrict__ Wk,
                         const float* __restrict__ Wv, const float* __restrict__ Wo,
                         __nv_bfloat16* __restrict__ Ah, __nv_bfloat16* __restrict__ Al,
                         __nv_bfloat16* __restrict__ Tch, __nv_bfloat16* __restrict__ Tcl,
                         __nv_bfloat16* __restrict__ Toh, __nv_bfloat16* __restrict__ Tol,
                         float2* __restrict__ rope)
{
    int bx = blockIdx.x;
    const int tid = threadIdx.y * 32 + threadIdx.x;
    if (bx >= 161) {
        const int c = (bx - 161) * 64 + blockIdx.y;
        const size_t base4 = ((size_t)c * 2048) / 4;
#pragma unroll
        for (int u = 0; u < 2; u++) {
            size_t i = base4 + u * 256 + tid;
            float4 v = reinterpret_cast<const float4*>(hs)[i];
            float f[4] = {v.x, v.y, v.z, v.w};
            __nv_bfloat16 hh[4], ll[4];
#pragma unroll
            for (int j = 0; j < 4; j++) {
                hh[j] = __float2bfloat16_rn(f[j]);
                ll[j] = __float2bfloat16_rn(f[j] - __bfloat162float(hh[j]));
            }
            reinterpret_cast<uint2*>(Ah)[i] = *reinterpret_cast<uint2*>(hh);
            reinterpret_cast<uint2*>(Al)[i] = *reinterpret_cast<uint2*>(ll);
        }
        return;
    }
    if (bx == 160) {
        if (blockIdx.y == 0) {
            if (tid < 32)      g_flagM[tid] = 0;
            else if (tid < 64) g_flagA[tid - 32] = 0;
        }
        int idx = (blockIdx.y * 256 + tid) * 4;
#pragma unroll
        for (int j = 0; j < 4; j++) {
            int id = idx + j;
            int s = id >> 5, pair = id & 31;
            float inv = powf(10000.f, -(float)(2 * pair) * (1.f / 64.f));
            float sn, c;
            sincosf((float)s * inv, &sn, &c);
            rope[id] = make_float2(c, sn);
        }
        return;
    }
    __shared__ float t[32][33];
    const float* W;
    __nv_bfloat16 *Th, *Tl;
    int N, rowoff;
    if (bx < 64)       { W = Wq; N = 2048; rowoff = 0;    Th = Tch; Tl = Tcl; }
    else if (bx < 80)  { W = Wk; N = 512;  rowoff = 2048; Th = Tch; Tl = Tcl; bx -= 64; }
    else if (bx < 96)  { W = Wv; N = 512;  rowoff = 2560; Th = Tch; Tl = Tcl; bx -= 80; }
    else               { W = Wo; N = 2048; rowoff = 0;    Th = Toh; Tl = Tol; bx -= 96; }
    const int n0 = bx * 32, k0 = blockIdx.y * 32;
    const int tx = threadIdx.x, ty = threadIdx.y;
#pragma unroll
    for (int i = 0; i < 4; i++)
        t[ty + 8 * i][tx] = W[(size_t)(k0 + ty + 8 * i) * N + n0 + tx];
    __syncthreads();
#pragma unroll
    for (int i = 0; i < 4; i++) {
        float v = t[tx][ty + 8 * i];
        __nv_bfloat16 h = __float2bfloat16_rn(v);
        __nv_bfloat16 l = __float2bfloat16_rn(v - __bfloat162float(h));
        size_t o = (size_t)(rowoff + n0 + ty + 8 * i) * DM + k0 + tx;
        Th[o] = h; Tl[o] = l;
    }
}

// ---------------------------------------------------------------------------
extern "C" void kernel_launch(void* const* d_in, const int* in_sizes, int n_in,
                              void* d_out, int out_size)
{
    const float* hs = (const float*)d_in[0];
    const float* Wq = (const float*)d_in[1];
    const float* Wk = (const float*)d_in[2];
    const float* Wv = (const float*)d_in[3];
    const float* Wo = (const float*)d_in[4];
    const float* bo = (const float*)d_in[5];
    float* out = (float*)d_out;

    __nv_bfloat16 *ah, *al, *wch, *wcl, *woh, *wol;
    float2* rope;
    cudaGetSymbolAddress((void**)&ah,  g_ah);
    cudaGetSymbolAddress((void**)&al,  g_al);
    cudaGetSymbolAddress((void**)&wch, g_wch);
    cudaGetSymbolAddress((void**)&wcl, g_wcl);
    cudaGetSymbolAddress((void**)&woh, g_woh);
    cudaGetSymbolAddress((void**)&wol, g_wol);
    cudaGetSymbolAddress((void**)&rope, g_rope);

    const int mega_smem = 3 * 32768;   // 96 KB
    cudaFuncSetAttribute(fused_mega, cudaFuncAttributeMaxDynamicSharedMemorySize, mega_smem);

    // launch 1: all prep concurrently
    prep_all<<<dim3(225, 64), dim3(32, 8)>>>(hs, Wq, Wk, Wv, Wo,
                                             ah, al, wch, wcl, woh, wol, rope);

    // launch 2: fused QKV-gemm -> attention -> out-proj (flag-synchronized)
    fused_mega<<<dim3(768 + 1024 + 512), 256, mega_smem>>>(bo, out);
}

// round 16
// speedup vs baseline: 1.3888x; 1.2674x over previous
#include <cuda_runtime.h>
#include <cuda_bf16.h>
#include <cuda_fp16.h>
#include <math.h>
#include <stdint.h>

#define DM    2048
#define SEQ   2048
#define BATCH 2
#define NH    32
#define NG    8
#define DH    64
#define MROWS (BATCH*SEQ)   // 4096
#define NQKV  3072

// ---------------- scratch (__device__ globals; no allocs allowed) ----------
__device__ __half g_ah[(size_t)MROWS*DM];   // A split fp16 hi/lo (hs, later ctx)
__device__ __half g_al[(size_t)MROWS*DM];
__device__ __half g_wc[(size_t)NQKV*DM];    // Wqkv^T single fp16
__device__ __half g_wo[(size_t)DM*DM];      // Wo^T single fp16
__device__ __half g_qh[(size_t)BATCH*NH*SEQ*DH], g_ql[(size_t)BATCH*NH*SEQ*DH];
__device__ __half g_kh[(size_t)BATCH*NG*SEQ*DH];
__device__ __half g_vh[(size_t)BATCH*NG*SEQ*DH], g_vl[(size_t)BATCH*NG*SEQ*DH];
__device__ float2 g_rope[SEQ * 32];
__device__ int g_flagM[32];   // per 128-row block: QKV N-tile arrivals (target 24)
__device__ int g_flagA[32];   // per 128-row block: attention head arrivals (target 32)

// ---------------- helpers ---------------------------------------------------
__device__ __forceinline__ uint32_t smem_u32(const void* p) {
    uint32_t a;
    asm("{ .reg .u64 t; cvta.to.shared.u64 t, %1; cvt.u32.u64 %0, t; }" : "=r"(a) : "l"(p));
    return a;
}
__device__ __forceinline__ void ldsm4(uint32_t* r, uint32_t addr) {
    asm volatile("ldmatrix.sync.aligned.m8n8.x4.shared.b16 {%0,%1,%2,%3}, [%4];"
                 : "=r"(r[0]), "=r"(r[1]), "=r"(r[2]), "=r"(r[3]) : "r"(addr));
}
__device__ __forceinline__ void ldsm4t(uint32_t* r, uint32_t addr) {
    asm volatile("ldmatrix.sync.aligned.m8n8.x4.trans.shared.b16 {%0,%1,%2,%3}, [%4];"
                 : "=r"(r[0]), "=r"(r[1]), "=r"(r[2]), "=r"(r[3]) : "r"(addr));
}
__device__ __forceinline__ void mma16816h(float* c, const uint32_t* a, const uint32_t* b) {
    asm volatile("mma.sync.aligned.m16n8k16.row.col.f32.f16.f16.f32 "
                 "{%0,%1,%2,%3}, {%4,%5,%6,%7}, {%8,%9}, {%0,%1,%2,%3};"
                 : "+f"(c[0]), "+f"(c[1]), "+f"(c[2]), "+f"(c[3])
                 : "r"(a[0]), "r"(a[1]), "r"(a[2]), "r"(a[3]), "r"(b[0]), "r"(b[1]));
}
#define CP_ASYNC16(s, g) \
    asm volatile("cp.async.cg.shared.global [%0], [%1], 16;" :: "r"(s), "l"(g))
#define CP_COMMIT() asm volatile("cp.async.commit_group;" ::: "memory")
#define CP_WAIT1()  asm volatile("cp.async.wait_group 1;" ::: "memory")

__device__ __forceinline__ uint32_t packh(float lo, float hi) {
    __half2 t = __floats2half2_rn(lo, hi);
    return *reinterpret_cast<uint32_t*>(&t);
}
__device__ __forceinline__ float ex2f(float x) {
    float r;
    asm("ex2.approx.ftz.f32 %0, %1;" : "=f"(r) : "f"(x));
    return r;
}
// p' = 2^40 * exp(30*tanh(s/30) - 30)  (fp16-safe scaling; cancels in oac/ls).
__device__ __forceinline__ float softmax_p(float sv) {
    const float s2 = sv * sv;
    const float P = fmaf(s2, fmaf(s2, 2.3748002e-7f, -5.3433150e-4f), 1.44269504f);
    return ex2f(fmaf(sv, P, -3.2808512f));
}
__device__ __forceinline__ void spin_ge(const int* f, int target) {
    const volatile int* vf = (const volatile int*)f;
    while (*vf < target) __nanosleep(128);
    __threadfence();
}

// ---------------------------------------------------------------------------
// fp16 HMMA GEMM tile: C = (Ah+Al) @ W^T, 2 MMAs per k-step.
// 128x128 CTA tile, BK=32, 3-stage ring (stage 24KB: Ah 8K, Al 8K, W 8K).
// mode 0: fp32 row-major + bias.
// mode 3: combined QKV epilogue -> Q fp16 hi/lo (rope), K fp16 (rope), V fp16 hi/lo.
// ---------------------------------------------------------------------------
__device__ __forceinline__ void gemm_tile(
    const __half* __restrict__ Ah, const __half* __restrict__ Al,
    const __half* __restrict__ Bw,
    float* __restrict__ Cf,
    __half* __restrict__ Qh, __half* __restrict__ Ql,
    __half* __restrict__ Kh,
    __half* __restrict__ Vh, __half* __restrict__ Vl,
    const float2* __restrict__ rope,
    int Ntot, int mode, const float* __restrict__ bias,
    int m0, int n0, char* smc)
{
    const uint32_t sbase = smem_u32(smc);
    const int tid = threadIdx.x, lane = tid & 31, wid = tid >> 5;
    const int wm = wid >> 2, wn = wid & 3;
    const int fr = tid >> 2;
    const int fc = tid & 3;

    uint32_t offA[4][2], offB[2][2];
#pragma unroll
    for (int mf = 0; mf < 4; mf++)
#pragma unroll
        for (int ks = 0; ks < 2; ks++) {
            int row = wm * 64 + mf * 16 + (lane & 7) + ((lane >> 3) & 1) * 8;
            int ch  = ks * 2 + (lane >> 4);
            offA[mf][ks] = row * 64 + ((ch ^ ((row >> 1) & 3)) << 4);
        }
#pragma unroll
    for (int np = 0; np < 2; np++)
#pragma unroll
        for (int ks = 0; ks < 2; ks++) {
            int row = wn * 32 + np * 16 + (lane & 7) + (lane >> 4) * 8;
            int ch  = ks * 2 + ((lane >> 3) & 1);
            offB[np][ks] = row * 64 + ((ch ^ ((row >> 1) & 3)) << 4);
        }

    float acc[4][4][4];
#pragma unroll
    for (int i = 0; i < 4; i++)
#pragma unroll
        for (int j = 0; j < 4; j++)
#pragma unroll
            for (int l = 0; l < 4; l++) acc[i][j][l] = 0.f;

    auto fill = [&](int kc, int stage) {
        const uint32_t sb = sbase + stage * 24576;
#pragma unroll
        for (int i = 0; i < 2; i++) {
            const int r = fr + i * 64;
            const uint32_t so = r * 64 + ((fc ^ ((r >> 1) & 3)) << 4);
            const size_t gA = (size_t)(m0 + r) * DM + kc * 32 + fc * 8;
            const size_t gB = (size_t)(n0 + r) * DM + kc * 32 + fc * 8;
            CP_ASYNC16(sb +         so, Ah + gA);
            CP_ASYNC16(sb +  8192 + so, Al + gA);
            CP_ASYNC16(sb + 16384 + so, Bw + gB);
        }
        CP_COMMIT();
    };

    fill(0, 0);
    fill(1, 1);

    const int NKC = DM / 32;
    int rd = 0, wr = 2;
    for (int kc = 0; kc < NKC; kc++) {
        CP_WAIT1();
        __syncthreads();
        const uint32_t sA = sbase + rd * 24576;
#pragma unroll
        for (int ks = 0; ks < 2; ks++) {
            uint32_t bh[2][4];
#pragma unroll
            for (int np = 0; np < 2; np++)
                ldsm4(bh[np], sA + 16384 + offB[np][ks]);
#pragma unroll
            for (int mf = 0; mf < 4; mf++) {
                uint32_t ah[4], al[4];
                ldsm4(ah, sA +        offA[mf][ks]);
                ldsm4(al, sA + 8192 + offA[mf][ks]);
#pragma unroll
                for (int nf = 0; nf < 4; nf++) {
                    const uint32_t* bhp = &bh[nf >> 1][(nf & 1) * 2];
                    mma16816h(acc[mf][nf], ah, bhp);
                    mma16816h(acc[mf][nf], al, bhp);
                }
            }
        }
        if (kc + 2 < NKC) fill(kc + 2, wr);
        else CP_COMMIT();
        rd = (rd == 2) ? 0 : rd + 1;
        wr = (wr == 2) ? 0 : wr + 1;
    }

    const int g4 = lane >> 2, t4 = lane & 3;
#pragma unroll
    for (int mf = 0; mf < 4; mf++) {
#pragma unroll
        for (int nf = 0; nf < 4; nf++) {
            const int row = m0 + wm * 64 + mf * 16 + g4;
            const int col = n0 + wn * 32 + nf * 8 + t4 * 2;
            float2 v0 = make_float2(acc[mf][nf][0], acc[mf][nf][1]);
            float2 v1 = make_float2(acc[mf][nf][2], acc[mf][nf][3]);
            if (mode == 0) {
                const float b0 = bias[col], b1 = bias[col + 1];
                v0.x += b0; v0.y += b1; v1.x += b0; v1.y += b1;
                *reinterpret_cast<float2*>(Cf + (size_t)row * Ntot + col)       = v0;
                *reinterpret_cast<float2*>(Cf + (size_t)(row + 8) * Ntot + col) = v1;
            } else {
                const int pair = (col & 63) >> 1;
                float2 vv[2] = {v0, v1};
#pragma unroll
                for (int t = 0; t < 2; t++) {
                    const int r = row + t * 8;
                    const int bb = r >> 11, s = r & (SEQ - 1);
                    float x0 = vv[t].x, x1 = vv[t].y;
                    if (col < 2560) {
                        float2 cs = rope[s * 32 + pair];
                        float r0 = x0 * cs.x - x1 * cs.y;
                        x1 = x1 * cs.x + x0 * cs.y;
                        x0 = r0;
                    }
                    if (col < 2048) {        // Q: fp16 hi/lo
                        const int hh = col >> 6;
                        size_t o32 = ((size_t)(bb * NH + hh) * SEQ + s) * 32 + pair;
                        __half h0 = __float2half_rn(x0), h1 = __float2half_rn(x1);
                        __half2 hp = __halves2half2(h0, h1);
                        reinterpret_cast<uint32_t*>(Qh)[o32] = *reinterpret_cast<uint32_t*>(&hp);
                        reinterpret_cast<uint32_t*>(Ql)[o32] =
                            packh(x0 - __half2float(h0), x1 - __half2float(h1));
                    } else if (col < 2560) { // K: fp16 single
                        const int hh = (col - 2048) >> 6;
                        size_t o32 = ((size_t)(bb * NG + hh) * SEQ + s) * 32 + pair;
                        reinterpret_cast<uint32_t*>(Kh)[o32] = packh(x0, x1);
                    } else {                 // V: fp16 hi/lo
                        const int hh = (col - 2560) >> 6;
                        size_t o32 = ((size_t)(bb * NG + hh) * SEQ + s) * 32 + pair;
                        __half h0 = __float2half_rn(x0), h1 = __float2half_rn(x1);
                        __half2 hp = __halves2half2(h0, h1);
                        reinterpret_cast<uint32_t*>(Vh)[o32] = *reinterpret_cast<uint32_t*>(&hp);
                        reinterpret_cast<uint32_t*>(Vl)[o32] =
                            packh(x0 - __half2float(h0), x1 - __half2float(h1));
                    }
                }
            }
        }
    }
}

// ---------------------------------------------------------------------------
// Attention tile: fp16 path (unchanged from R15). Output ctx fp16 hi/lo.
// ---------------------------------------------------------------------------
__device__ __forceinline__ void attn_tile(
    int a,
    const __half* __restrict__ Qh, const __half* __restrict__ Ql,
    const __half* __restrict__ Kh,
    const __half* __restrict__ Vh, const __half* __restrict__ Vl,
    __half* __restrict__ Ch, __half* __restrict__ Cl, char* smc)
{
    const uint32_t sb = smem_u32(smc);
    const int tid = threadIdx.x, lane = tid & 31, wid = tid >> 5;
    const int qt  = (SEQ / 128 - 1) - (a >> 6);
    const int sub = a & 63;
    const int h = sub >> 1, b = sub & 1;
    const int g = h >> 2;
    const int q0 = qt << 7;
    const int wrow = wid * 16;

    const size_t qbase = ((size_t)(b * NH + h) * SEQ + q0) * DH;
    const size_t kbase = ((size_t)(b * NG + g) * SEQ) * DH;

    constexpr uint32_t SQH = 0, SQL = 16384, SST = 32768, STAGE = 24576;

    const int fbase = b << 4;
    bool allM = true;
    {
        const volatile int* vf = (const volatile int*)g_flagM;
        for (int j = 0; j <= qt; j++) allM &= (vf[fbase + j] >= 24);
    }
    __threadfence();

    if (!allM) spin_ge(&g_flagM[fbase + qt], 24);
    {
#pragma unroll
        for (int i = 0; i < 4; i++) {
            int idx = tid + (i << 8);
            int r = idx >> 3, ch = idx & 7;
            uint32_t so = r * 128 + ((ch ^ (r & 7)) << 4);
            CP_ASYNC16(sb + SQH + so, Qh + qbase + r * 64 + ch * 8);
            CP_ASYNC16(sb + SQL + so, Ql + qbase + r * 64 + ch * 8);
        }
        CP_COMMIT();
    }
    auto fillkv = [&](int kt, int st) {
        const uint32_t s0 = sb + SST + st * STAGE;
        const size_t kb = kbase + (size_t)kt * 64 * 64;
#pragma unroll
        for (int i = 0; i < 2; i++) {
            int idx = tid + (i << 8);
            int r = idx >> 3, ch = idx & 7;
            uint32_t so = r * 128 + ((ch ^ (r & 7)) << 4);
            size_t go = kb + r * 64 + ch * 8;
            CP_ASYNC16(s0 +         so, Kh + go);
            CP_ASYNC16(s0 +  8192 + so, Vh + go);
            CP_ASYNC16(s0 + 16384 + so, Vl + go);
        }
        CP_COMMIT();
    };
    const int nkt = (qt + 1) * 2;
    const int hi = nkt - 1;
    if (!allM) spin_ge(&g_flagM[fbase + (hi >> 1)], 24);
    fillkv(hi, hi & 1);
    if (hi >= 1) {
        if (!allM) spin_ge(&g_flagM[fbase + ((hi - 1) >> 1)], 24);
        fillkv(hi - 1, (hi - 1) & 1);
    } else CP_COMMIT();

    uint32_t qoff[4];
    {
        const int row = wrow + (lane & 7) + ((lane >> 3) & 1) * 8;
        const int chb = lane >> 4;
#pragma unroll
        for (int ks = 0; ks < 4; ks++)
            qoff[ks] = row * 128 + (((ks * 2 + chb) ^ (row & 7)) << 4);
    }

    float oac[8][4];
#pragma unroll
    for (int i = 0; i < 8; i++)
#pragma unroll
        for (int j = 0; j < 4; j++) oac[i][j] = 0.f;
    float ls0 = 0.f, ls1 = 0.f;
    const float slope8 = exp2f(-(float)(h + 1) * 0.25f) * 0.125f;
    const int qr = q0 + wrow + (lane >> 2);

    const int klrow = (lane & 7) + ((lane >> 4) << 3);
    const int klchb = (lane >> 3) & 1;
    const int vlrow = (lane & 7) + (((lane >> 3) & 1) << 3);
    const int vlchb = lane >> 4;

    for (int kt = hi; kt >= 0; kt--) {
        const int st = kt & 1;
        const uint32_t sK = sb + SST + st * STAGE;
        CP_WAIT1();
        __syncthreads();

        if ((kt << 6) <= q0 + wrow + 15) {
            float sc[8][4];
#pragma unroll
            for (int i = 0; i < 8; i++)
#pragma unroll
                for (int j = 0; j < 4; j++) sc[i][j] = 0.f;

#pragma unroll
            for (int ks = 0; ks < 4; ks++) {
                uint32_t qh_t[4], ql_t[4];
                ldsm4(qh_t, sb + SQH + qoff[ks]);
                ldsm4(ql_t, sb + SQL + qoff[ks]);
#pragma unroll
                for (int ng = 0; ng < 4; ng++) {
                    const int row = ng * 16 + klrow;
                    const uint32_t so = row * 128 + (((ks * 2 + klchb) ^ (row & 7)) << 4);
                    uint32_t kf[4];
                    ldsm4(kf, sK + so);
                    mma16816h(sc[ng * 2],     qh_t, kf);
                    mma16816h(sc[ng * 2],     ql_t, kf);
                    mma16816h(sc[ng * 2 + 1], qh_t, kf + 2);
                    mma16816h(sc[ng * 2 + 1], ql_t, kf + 2);
                }
            }

            const int kcol0 = (kt << 6) + (lane & 3) * 2;
            const bool tail = ((kt << 6) + 63 > q0 + wrow);
#pragma unroll
            for (int nf = 0; nf < 8; nf++) {
                const int kc = kcol0 + nf * 8;
                const float bias0 = slope8 * (float)(kc - qr);
                float p0 = softmax_p(fmaf(sc[nf][0], 0.125f, bias0));
                float p1 = softmax_p(fmaf(sc[nf][1], 0.125f, bias0 + slope8));
                float p2 = softmax_p(fmaf(sc[nf][2], 0.125f, bias0 - 8.f * slope8));
                float p3 = softmax_p(fmaf(sc[nf][3], 0.125f, bias0 - 7.f * slope8));
                if (tail) {
                    if (kc > qr)         p0 = 0.f;
                    if (kc + 1 > qr)     p1 = 0.f;
                    if (kc > qr + 8)     p2 = 0.f;
                    if (kc + 1 > qr + 8) p3 = 0.f;
                }
                ls0 += p0 + p1;
                ls1 += p2 + p3;
                sc[nf][0] = p0; sc[nf][1] = p1; sc[nf][2] = p2; sc[nf][3] = p3;
            }

#pragma unroll
            for (int j = 0; j < 4; j++) {
                uint32_t pa[4];
                pa[0] = packh(sc[2 * j][0],     sc[2 * j][1]);
                pa[1] = packh(sc[2 * j][2],     sc[2 * j][3]);
                pa[2] = packh(sc[2 * j + 1][0], sc[2 * j + 1][1]);
                pa[3] = packh(sc[2 * j + 1][2], sc[2 * j + 1][3]);
#pragma unroll
                for (int gD = 0; gD < 4; gD++) {
                    const int row = j * 16 + vlrow;
                    const uint32_t so = row * 128 + (((gD * 2 + vlchb) ^ (row & 7)) << 4);
                    uint32_t vfh[4], vfl[4];
                    ldsm4t(vfh, sK +  8192 + so);
                    ldsm4t(vfl, sK + 16384 + so);
                    mma16816h(oac[gD * 2],     pa, vfh);
                    mma16816h(oac[gD * 2],     pa, vfl);
                    mma16816h(oac[gD * 2 + 1], pa, vfh + 2);
                    mma16816h(oac[gD * 2 + 1], pa, vfl + 2);
                }
            }
        }
        __syncthreads();
        if (kt - 2 >= 0) {
            if (!allM) spin_ge(&g_flagM[fbase + ((kt - 2) >> 1)], 24);
            fillkv(kt - 2, st);
        } else CP_COMMIT();
    }

    ls0 += __shfl_xor_sync(0xffffffffu, ls0, 1);
    ls0 += __shfl_xor_sync(0xffffffffu, ls0, 2);
    ls1 += __shfl_xor_sync(0xffffffffu, ls1, 1);
    ls1 += __shfl_xor_sync(0xffffffffu, ls1, 2);
    const float inv0 = 1.f / ls0, inv1 = 1.f / ls1;

    const size_t rowM0 = (size_t)b * SEQ + qr;
#pragma unroll
    for (int nf = 0; nf < 8; nf++) {
        const int col = h * 64 + nf * 8 + (lane & 3) * 2;
        float x0 = oac[nf][0] * inv0, x1 = oac[nf][1] * inv0;
        float y0 = oac[nf][2] * inv1, y1 = oac[nf][3] * inv1;
        __half hx0 = __float2half_rn(x0), hx1 = __float2half_rn(x1);
        __half hy0 = __float2half_rn(y0), hy1 = __float2half_rn(y1);
        size_t o0 = (rowM0 * DM + col) >> 1;
        size_t o1 = ((rowM0 + 8) * DM + col) >> 1;
        __half2 hp0 = __halves2half2(hx0, hx1);
        __half2 hp1 = __halves2half2(hy0, hy1);
        reinterpret_cast<uint32_t*>(Ch)[o0] = *reinterpret_cast<uint32_t*>(&hp0);
        reinterpret_cast<uint32_t*>(Cl)[o0] = packh(x0 - __half2float(hx0), x1 - __half2float(hx1));
        reinterpret_cast<uint32_t*>(Ch)[o1] = *reinterpret_cast<uint32_t*>(&hp1);
        reinterpret_cast<uint32_t*>(Cl)[o1] = packh(y0 - __half2float(hy0), y1 - __half2float(hy1));
    }
    __threadfence();
    __syncthreads();
    if (tid == 0) atomicAdd(&g_flagA[fbase + qt], 1);
}

// ---------------------------------------------------------------------------
// Fused mega-kernel: QKV gemm tiles -> attention -> out-proj, flag-synced.
// ---------------------------------------------------------------------------
__global__ __launch_bounds__(256, 2)
void fused_mega(const float* __restrict__ bo, float* __restrict__ out)
{
    extern __shared__ __align__(128) char smc[];
    const int bid = blockIdx.x;

    if (bid < 768) {
        const int nt = bid % 24, y = bid / 24;
        const int sblk = 15 - (y >> 1), bq = y & 1;
        const int m0 = ((bq << 4) + sblk) << 7;
        gemm_tile(g_ah, g_al, g_wc, nullptr,
                  g_qh, g_ql, g_kh, g_vh, g_vl, g_rope,
                  NQKV, 3, nullptr, m0, nt << 7, smc);
        __threadfence();
        __syncthreads();
        if (threadIdx.x == 0) atomicAdd(&g_flagM[m0 >> 7], 1);
    } else if (bid < 1792) {
        attn_tile(bid - 768, g_qh, g_ql, g_kh, g_vh, g_vl, g_ah, g_al, smc);
    } else {
        const int o = bid - 1792;
        const int mi = o >> 4, nb = o & 15;
        const int qtm = 15 - (mi >> 1), bm = mi & 1;
        const int m0 = ((bm << 4) + qtm) << 7;
        spin_ge(&g_flagA[m0 >> 7], 32);
        gemm_tile(g_ah, g_al, g_wo, out,
                  nullptr, nullptr, nullptr, nullptr, nullptr, nullptr,
                  DM, 0, bo, m0, nb << 7, smc);
    }
}

// ---------------------------------------------------------------------------
// ONE prep launch: weight transposes (single fp16) + hs split (fp16 hi/lo)
// + rope table + flag zeroing.
// ---------------------------------------------------------------------------
__global__ void prep_all(const float* __restrict__ hs,
                         const float* __restrict__ Wq, const float* __restrict__ Wk,
                         const float* __restrict__ Wv, const float* __restrict__ Wo,
                         __half* __restrict__ Ah, __half* __restrict__ Al,
                         __half* __restrict__ Tc, __half* __restrict__ To,
                         float2* __restrict__ rope)
{
    int bx = blockIdx.x;
    const int tid = threadIdx.y * 32 + threadIdx.x;
    if (bx >= 161) {
        const int c = (bx - 161) * 64 + blockIdx.y;
        const size_t base4 = ((size_t)c * 2048) / 4;
#pragma unroll
        for (int u = 0; u < 2; u++) {
            size_t i = base4 + u * 256 + tid;
            float4 v = reinterpret_cast<const float4*>(hs)[i];
            float f[4] = {v.x, v.y, v.z, v.w};
            __half hh[4], ll[4];
#pragma unroll
            for (int j = 0; j < 4; j++) {
                hh[j] = __float2half_rn(f[j]);
                ll[j] = __float2half_rn(f[j] - __half2float(hh[j]));
            }
            reinterpret_cast<uint2*>(Ah)[i] = *reinterpret_cast<uint2*>(hh);
            reinterpret_cast<uint2*>(Al)[i] = *reinterpret_cast<uint2*>(ll);
        }
        return;
    }
    if (bx == 160) {
        if (blockIdx.y == 0) {
            if (tid < 32)      g_flagM[tid] = 0;
            else if (tid < 64) g_flagA[tid - 32] = 0;
        }
        int idx = (blockIdx.y * 256 + tid) * 4;
#pragma unroll
        for (int j = 0; j < 4; j++) {
            int id = idx + j;
            int s = id >> 5, pair = id & 31;
            float inv = powf(10000.f, -(float)(2 * pair) * (1.f / 64.f));
            float sn, c;
            sincosf((float)s * inv, &sn, &c);
            rope[id] = make_float2(c, sn);
        }
        return;
    }
    __shared__ float t[32][33];
    const float* W;
    __half* Th;
    int N, rowoff;
    if (bx < 64)       { W = Wq; N = 2048; rowoff = 0;    Th = Tc; }
    else if (bx < 80)  { W = Wk; N = 512;  rowoff = 2048; Th = Tc; bx -= 64; }
    else if (bx < 96)  { W = Wv; N = 512;  rowoff = 2560; Th = Tc; bx -= 80; }
    else               { W = Wo; N = 2048; rowoff = 0;    Th = To; bx -= 96; }
    const int n0 = bx * 32, k0 = blockIdx.y * 32;
    const int tx = threadIdx.x, ty = threadIdx.y;
#pragma unroll
    for (int i = 0; i < 4; i++)
        t[ty + 8 * i][tx] = W[(size_t)(k0 + ty + 8 * i) * N + n0 + tx];
    __syncthreads();
#pragma unroll
    for (int i = 0; i < 4; i++) {
        float v = t[tx][ty + 8 * i];
        size_t o = (size_t)(rowoff + n0 + ty + 8 * i) * DM + k0 + tx;
        Th[o] = __float2half_rn(v);
    }
}

// ---------------------------------------------------------------------------
extern "C" void kernel_launch(void* const* d_in, const int* in_sizes, int n_in,
                              void* d_out, int out_size)
{
    const float* hs = (const float*)d_in[0];
    const float* Wq = (const float*)d_in[1];
    const float* Wk = (const float*)d_in[2];
    const float* Wv = (const float*)d_in[3];
    const float* Wo = (const float*)d_in[4];
    const float* bo = (const float*)d_in[5];
    float* out = (float*)d_out;

    __half *ah, *al, *wc, *wo;
    float2* rope;
    cudaGetSymbolAddress((void**)&ah, g_ah);
    cudaGetSymbolAddress((void**)&al, g_al);
    cudaGetSymbolAddress((void**)&wc, g_wc);
    cudaGetSymbolAddress((void**)&wo, g_wo);
    cudaGetSymbolAddress((void**)&rope, g_rope);

    const int mega_smem = 32768 + 2 * 24576;   // 81920 (attn); gemm uses 73728
    cudaFuncSetAttribute(fused_mega, cudaFuncAttributeMaxDynamicSharedMemorySize, mega_smem);

    // launch 1: all prep concurrently
    prep_all<<<dim3(225, 64), dim3(32, 8)>>>(hs, Wq, Wk, Wv, Wo,
                                             ah, al, wc, wo, rope);

    // launch 2: fused QKV-gemm -> attention -> out-proj (flag-synchronized)
    fused_mega<<<dim3(768 + 1024 + 512), 256, mega_smem>>>(bo, out);
}

// round 17
// speedup vs baseline: 1.4539x; 1.0469x over previous
#include <cuda_runtime.h>
#include <cuda_bf16.h>
#include <cuda_fp16.h>
#include <math.h>
#include <stdint.h>

#define DM    2048
#define SEQ   2048
#define BATCH 2
#define NH    32
#define NG    8
#define DH    64
#define MROWS (BATCH*SEQ)   // 4096
#define NQKV  3072

// ---------------- scratch (__device__ globals; no allocs allowed) ----------
__device__ __half g_ah[(size_t)MROWS*DM];   // A split fp16 hi/lo (hs, later ctx)
__device__ __half g_al[(size_t)MROWS*DM];
__device__ __half g_wc[(size_t)NQKV*DM];    // Wqkv^T single fp16
__device__ __half g_wo[(size_t)DM*DM];      // Wo^T single fp16
__device__ __half g_qh[(size_t)BATCH*NH*SEQ*DH];          // Q single fp16
__device__ __half g_kh[(size_t)BATCH*NG*SEQ*DH];          // K single fp16
__device__ __half g_vh[(size_t)BATCH*NG*SEQ*DH], g_vl[(size_t)BATCH*NG*SEQ*DH];
__device__ float2 g_rope[SEQ * 32];
__device__ int g_flagM[32];   // per 128-row block: QKV N-tile arrivals (target 24)
__device__ int g_flagA[32];   // per 128-row block: attention head arrivals (target 32)

// ---------------- helpers ---------------------------------------------------
__device__ __forceinline__ uint32_t smem_u32(const void* p) {
    uint32_t a;
    asm("{ .reg .u64 t; cvta.to.shared.u64 t, %1; cvt.u32.u64 %0, t; }" : "=r"(a) : "l"(p));
    return a;
}
__device__ __forceinline__ void ldsm4(uint32_t* r, uint32_t addr) {
    asm volatile("ldmatrix.sync.aligned.m8n8.x4.shared.b16 {%0,%1,%2,%3}, [%4];"
                 : "=r"(r[0]), "=r"(r[1]), "=r"(r[2]), "=r"(r[3]) : "r"(addr));
}
__device__ __forceinline__ void ldsm4t(uint32_t* r, uint32_t addr) {
    asm volatile("ldmatrix.sync.aligned.m8n8.x4.trans.shared.b16 {%0,%1,%2,%3}, [%4];"
                 : "=r"(r[0]), "=r"(r[1]), "=r"(r[2]), "=r"(r[3]) : "r"(addr));
}
__device__ __forceinline__ void mma16816h(float* c, const uint32_t* a, const uint32_t* b) {
    asm volatile("mma.sync.aligned.m16n8k16.row.col.f32.f16.f16.f32 "
                 "{%0,%1,%2,%3}, {%4,%5,%6,%7}, {%8,%9}, {%0,%1,%2,%3};"
                 : "+f"(c[0]), "+f"(c[1]), "+f"(c[2]), "+f"(c[3])
                 : "r"(a[0]), "r"(a[1]), "r"(a[2]), "r"(a[3]), "r"(b[0]), "r"(b[1]));
}
#define CP_ASYNC16(s, g) \
    asm volatile("cp.async.cg.shared.global [%0], [%1], 16;" :: "r"(s), "l"(g))
#define CP_COMMIT() asm volatile("cp.async.commit_group;" ::: "memory")
#define CP_WAIT1()  asm volatile("cp.async.wait_group 1;" ::: "memory")

__device__ __forceinline__ uint32_t packh(float lo, float hi) {
    __half2 t = __floats2half2_rn(lo, hi);
    return *reinterpret_cast<uint32_t*>(&t);
}
__device__ __forceinline__ float ex2f(float x) {
    float r;
    asm("ex2.approx.ftz.f32 %0, %1;" : "=f"(r) : "f"(x));
    return r;
}
// p' = 2^40 * exp(30*tanh(s/30) - 30)  (fp16-safe scaling; cancels in oac/ls).
__device__ __forceinline__ float softmax_p(float sv) {
    const float s2 = sv * sv;
    const float P = fmaf(s2, fmaf(s2, 2.3748002e-7f, -5.3433150e-4f), 1.44269504f);
    return ex2f(fmaf(sv, P, -3.2808512f));
}
__device__ __forceinline__ void spin_ge(const int* f, int target) {
    const volatile int* vf = (const volatile int*)f;
    while (*vf < target) __nanosleep(128);
    __threadfence();
}

// ---------------------------------------------------------------------------
// fp16 HMMA GEMM tile: C = (Ah+Al) @ W^T, 2 MMAs per k-step.
// 128x128 CTA tile, BK=32, 3-stage ring (stage 24KB).
// mode 0: fp32 row-major + bias.
// mode 3: QKV epilogue -> Q fp16 (rope), K fp16 (rope), V fp16 hi/lo.
// ---------------------------------------------------------------------------
__device__ __forceinline__ void gemm_tile(
    const __half* __restrict__ Ah, const __half* __restrict__ Al,
    const __half* __restrict__ Bw,
    float* __restrict__ Cf,
    __half* __restrict__ Qh,
    __half* __restrict__ Kh,
    __half* __restrict__ Vh, __half* __restrict__ Vl,
    const float2* __restrict__ rope,
    int Ntot, int mode, const float* __restrict__ bias,
    int m0, int n0, char* smc)
{
    const uint32_t sbase = smem_u32(smc);
    const int tid = threadIdx.x, lane = tid & 31, wid = tid >> 5;
    const int wm = wid >> 2, wn = wid & 3;
    const int fr = tid >> 2;
    const int fc = tid & 3;

    uint32_t offA[4][2], offB[2][2];
#pragma unroll
    for (int mf = 0; mf < 4; mf++)
#pragma unroll
        for (int ks = 0; ks < 2; ks++) {
            int row = wm * 64 + mf * 16 + (lane & 7) + ((lane >> 3) & 1) * 8;
            int ch  = ks * 2 + (lane >> 4);
            offA[mf][ks] = row * 64 + ((ch ^ ((row >> 1) & 3)) << 4);
        }
#pragma unroll
    for (int np = 0; np < 2; np++)
#pragma unroll
        for (int ks = 0; ks < 2; ks++) {
            int row = wn * 32 + np * 16 + (lane & 7) + (lane >> 4) * 8;
            int ch  = ks * 2 + ((lane >> 3) & 1);
            offB[np][ks] = row * 64 + ((ch ^ ((row >> 1) & 3)) << 4);
        }

    float acc[4][4][4];
#pragma unroll
    for (int i = 0; i < 4; i++)
#pragma unroll
        for (int j = 0; j < 4; j++)
#pragma unroll
            for (int l = 0; l < 4; l++) acc[i][j][l] = 0.f;

    auto fill = [&](int kc, int stage) {
        const uint32_t sb = sbase + stage * 24576;
#pragma unroll
        for (int i = 0; i < 2; i++) {
            const int r = fr + i * 64;
            const uint32_t so = r * 64 + ((fc ^ ((r >> 1) & 3)) << 4);
            const size_t gA = (size_t)(m0 + r) * DM + kc * 32 + fc * 8;
            const size_t gB = (size_t)(n0 + r) * DM + kc * 32 + fc * 8;
            CP_ASYNC16(sb +         so, Ah + gA);
            CP_ASYNC16(sb +  8192 + so, Al + gA);
            CP_ASYNC16(sb + 16384 + so, Bw + gB);
        }
        CP_COMMIT();
    };

    fill(0, 0);
    fill(1, 1);

    const int NKC = DM / 32;
    int rd = 0, wr = 2;
    for (int kc = 0; kc < NKC; kc++) {
        CP_WAIT1();
        __syncthreads();
        const uint32_t sA = sbase + rd * 24576;
#pragma unroll
        for (int ks = 0; ks < 2; ks++) {
            uint32_t bh[2][4];
#pragma unroll
            for (int np = 0; np < 2; np++)
                ldsm4(bh[np], sA + 16384 + offB[np][ks]);
#pragma unroll
            for (int mf = 0; mf < 4; mf++) {
                uint32_t ah[4], al[4];
                ldsm4(ah, sA +        offA[mf][ks]);
                ldsm4(al, sA + 8192 + offA[mf][ks]);
#pragma unroll
                for (int nf = 0; nf < 4; nf++) {
                    const uint32_t* bhp = &bh[nf >> 1][(nf & 1) * 2];
                    mma16816h(acc[mf][nf], ah, bhp);
                    mma16816h(acc[mf][nf], al, bhp);
                }
            }
        }
        if (kc + 2 < NKC) fill(kc + 2, wr);
        else CP_COMMIT();
        rd = (rd == 2) ? 0 : rd + 1;
        wr = (wr == 2) ? 0 : wr + 1;
    }

    const int g4 = lane >> 2, t4 = lane & 3;
#pragma unroll
    for (int mf = 0; mf < 4; mf++) {
#pragma unroll
        for (int nf = 0; nf < 4; nf++) {
            const int row = m0 + wm * 64 + mf * 16 + g4;
            const int col = n0 + wn * 32 + nf * 8 + t4 * 2;
            float2 v0 = make_float2(acc[mf][nf][0], acc[mf][nf][1]);
            float2 v1 = make_float2(acc[mf][nf][2], acc[mf][nf][3]);
            if (mode == 0) {
                const float b0 = bias[col], b1 = bias[col + 1];
                v0.x += b0; v0.y += b1; v1.x += b0; v1.y += b1;
                *reinterpret_cast<float2*>(Cf + (size_t)row * Ntot + col)       = v0;
                *reinterpret_cast<float2*>(Cf + (size_t)(row + 8) * Ntot + col) = v1;
            } else {
                const int pair = (col & 63) >> 1;
                float2 vv[2] = {v0, v1};
#pragma unroll
                for (int t = 0; t < 2; t++) {
                    const int r = row + t * 8;
                    const int bb = r >> 11, s = r & (SEQ - 1);
                    float x0 = vv[t].x, x1 = vv[t].y;
                    if (col < 2560) {
                        float2 cs = rope[s * 32 + pair];
                        float r0 = x0 * cs.x - x1 * cs.y;
                        x1 = x1 * cs.x + x0 * cs.y;
                        x0 = r0;
                    }
                    if (col < 2048) {        // Q: fp16 single
                        const int hh = col >> 6;
                        size_t o32 = ((size_t)(bb * NH + hh) * SEQ + s) * 32 + pair;
                        reinterpret_cast<uint32_t*>(Qh)[o32] = packh(x0, x1);
                    } else if (col < 2560) { // K: fp16 single
                        const int hh = (col - 2048) >> 6;
                        size_t o32 = ((size_t)(bb * NG + hh) * SEQ + s) * 32 + pair;
                        reinterpret_cast<uint32_t*>(Kh)[o32] = packh(x0, x1);
                    } else {                 // V: fp16 hi/lo
                        const int hh = (col - 2560) >> 6;
                        size_t o32 = ((size_t)(bb * NG + hh) * SEQ + s) * 32 + pair;
                        __half h0 = __float2half_rn(x0), h1 = __float2half_rn(x1);
                        __half2 hp = __halves2half2(h0, h1);
                        reinterpret_cast<uint32_t*>(Vh)[o32] = *reinterpret_cast<uint32_t*>(&hp);
                        reinterpret_cast<uint32_t*>(Vl)[o32] =
                            packh(x0 - __half2float(h0), x1 - __half2float(h1));
                    }
                }
            }
        }
    }
}

// ---------------------------------------------------------------------------
// Attention tile: Q single fp16 (S = 1 MMA/frag), P single, V hi/lo.
// smem: Q 16K + 2 stages x 24K = 64K.
// ---------------------------------------------------------------------------
__device__ __forceinline__ void attn_tile(
    int a,
    const __half* __restrict__ Qh,
    const __half* __restrict__ Kh,
    const __half* __restrict__ Vh, const __half* __restrict__ Vl,
    __half* __restrict__ Ch, __half* __restrict__ Cl, char* smc)
{
    const uint32_t sb = smem_u32(smc);
    const int tid = threadIdx.x, lane = tid & 31, wid = tid >> 5;
    const int qt  = (SEQ / 128 - 1) - (a >> 6);
    const int sub = a & 63;
    const int h = sub >> 1, b = sub & 1;
    const int g = h >> 2;
    const int q0 = qt << 7;
    const int wrow = wid * 16;

    const size_t qbase = ((size_t)(b * NH + h) * SEQ + q0) * DH;
    const size_t kbase = ((size_t)(b * NG + g) * SEQ) * DH;

    constexpr uint32_t SQH = 0, SST = 16384, STAGE = 24576;

    const int fbase = b << 4;
    bool allM = true;
    {
        const volatile int* vf = (const volatile int*)g_flagM;
        for (int j = 0; j <= qt; j++) allM &= (vf[fbase + j] >= 24);
    }
    __threadfence();

    if (!allM) spin_ge(&g_flagM[fbase + qt], 24);
    {
#pragma unroll
        for (int i = 0; i < 4; i++) {
            int idx = tid + (i << 8);
            int r = idx >> 3, ch = idx & 7;
            uint32_t so = r * 128 + ((ch ^ (r & 7)) << 4);
            CP_ASYNC16(sb + SQH + so, Qh + qbase + r * 64 + ch * 8);
        }
        CP_COMMIT();
    }
    auto fillkv = [&](int kt, int st) {
        const uint32_t s0 = sb + SST + st * STAGE;
        const size_t kb = kbase + (size_t)kt * 64 * 64;
#pragma unroll
        for (int i = 0; i < 2; i++) {
            int idx = tid + (i << 8);
            int r = idx >> 3, ch = idx & 7;
            uint32_t so = r * 128 + ((ch ^ (r & 7)) << 4);
            size_t go = kb + r * 64 + ch * 8;
            CP_ASYNC16(s0 +         so, Kh + go);
            CP_ASYNC16(s0 +  8192 + so, Vh + go);
            CP_ASYNC16(s0 + 16384 + so, Vl + go);
        }
        CP_COMMIT();
    };
    const int nkt = (qt + 1) * 2;
    const int hi = nkt - 1;
    if (!allM) spin_ge(&g_flagM[fbase + (hi >> 1)], 24);
    fillkv(hi, hi & 1);
    if (hi >= 1) {
        if (!allM) spin_ge(&g_flagM[fbase + ((hi - 1) >> 1)], 24);
        fillkv(hi - 1, (hi - 1) & 1);
    } else CP_COMMIT();

    uint32_t qoff[4];
    {
        const int row = wrow + (lane & 7) + ((lane >> 3) & 1) * 8;
        const int chb = lane >> 4;
#pragma unroll
        for (int ks = 0; ks < 4; ks++)
            qoff[ks] = row * 128 + (((ks * 2 + chb) ^ (row & 7)) << 4);
    }

    float oac[8][4];
#pragma unroll
    for (int i = 0; i < 8; i++)
#pragma unroll
        for (int j = 0; j < 4; j++) oac[i][j] = 0.f;
    float ls0 = 0.f, ls1 = 0.f;
    const float slope8 = exp2f(-(float)(h + 1) * 0.25f) * 0.125f;
    const int qr = q0 + wrow + (lane >> 2);

    const int klrow = (lane & 7) + ((lane >> 4) << 3);
    const int klchb = (lane >> 3) & 1;
    const int vlrow = (lane & 7) + (((lane >> 3) & 1) << 3);
    const int vlchb = lane >> 4;

    for (int kt = hi; kt >= 0; kt--) {
        const int st = kt & 1;
        const uint32_t sK = sb + SST + st * STAGE;
        CP_WAIT1();
        __syncthreads();

        if ((kt << 6) <= q0 + wrow + 15) {
            float sc[8][4];
#pragma unroll
            for (int i = 0; i < 8; i++)
#pragma unroll
                for (int j = 0; j < 4; j++) sc[i][j] = 0.f;

#pragma unroll
            for (int ks = 0; ks < 4; ks++) {
                uint32_t qf[4];
                ldsm4(qf, sb + SQH + qoff[ks]);
#pragma unroll
                for (int ng = 0; ng < 4; ng++) {
                    const int row = ng * 16 + klrow;
                    const uint32_t so = row * 128 + (((ks * 2 + klchb) ^ (row & 7)) << 4);
                    uint32_t kf[4];
                    ldsm4(kf, sK + so);
                    mma16816h(sc[ng * 2],     qf, kf);
                    mma16816h(sc[ng * 2 + 1], qf, kf + 2);
                }
            }

            const int kcol0 = (kt << 6) + (lane & 3) * 2;
            const bool tail = ((kt << 6) + 63 > q0 + wrow);
#pragma unroll
            for (int nf = 0; nf < 8; nf++) {
                const int kc = kcol0 + nf * 8;
                const float bias0 = slope8 * (float)(kc - qr);
                float p0 = softmax_p(fmaf(sc[nf][0], 0.125f, bias0));
                float p1 = softmax_p(fmaf(sc[nf][1], 0.125f, bias0 + slope8));
                float p2 = softmax_p(fmaf(sc[nf][2], 0.125f, bias0 - 8.f * slope8));
                float p3 = softmax_p(fmaf(sc[nf][3], 0.125f, bias0 - 7.f * slope8));
                if (tail) {
                    if (kc > qr)         p0 = 0.f;
                    if (kc + 1 > qr)     p1 = 0.f;
                    if (kc > qr + 8)     p2 = 0.f;
                    if (kc + 1 > qr + 8) p3 = 0.f;
                }
                ls0 += p0 + p1;
                ls1 += p2 + p3;
                sc[nf][0] = p0; sc[nf][1] = p1; sc[nf][2] = p2; sc[nf][3] = p3;
            }

#pragma unroll
            for (int j = 0; j < 4; j++) {
                uint32_t pa[4];
                pa[0] = packh(sc[2 * j][0],     sc[2 * j][1]);
                pa[1] = packh(sc[2 * j][2],     sc[2 * j][3]);
                pa[2] = packh(sc[2 * j + 1][0], sc[2 * j + 1][1]);
                pa[3] = packh(sc[2 * j + 1][2], sc[2 * j + 1][3]);
#pragma unroll
                for (int gD = 0; gD < 4; gD++) {
                    const int row = j * 16 + vlrow;
                    const uint32_t so = row * 128 + (((gD * 2 + vlchb) ^ (row & 7)) << 4);
                    uint32_t vfh[4], vfl[4];
                    ldsm4t(vfh, sK +  8192 + so);
                    ldsm4t(vfl, sK + 16384 + so);
                    mma16816h(oac[gD * 2],     pa, vfh);
                    mma16816h(oac[gD * 2],     pa, vfl);
                    mma16816h(oac[gD * 2 + 1], pa, vfh + 2);
                    mma16816h(oac[gD * 2 + 1], pa, vfl + 2);
                }
            }
        }
        __syncthreads();
        if (kt - 2 >= 0) {
            if (!allM) spin_ge(&g_flagM[fbase + ((kt - 2) >> 1)], 24);
            fillkv(kt - 2, st);
        } else CP_COMMIT();
    }

    ls0 += __shfl_xor_sync(0xffffffffu, ls0, 1);
    ls0 += __shfl_xor_sync(0xffffffffu, ls0, 2);
    ls1 += __shfl_xor_sync(0xffffffffu, ls1, 1);
    ls1 += __shfl_xor_sync(0xffffffffu, ls1, 2);
    const float inv0 = 1.f / ls0, inv1 = 1.f / ls1;

    const size_t rowM0 = (size_t)b * SEQ + qr;
#pragma unroll
    for (int nf = 0; nf < 8; nf++) {
        const int col = h * 64 + nf * 8 + (lane & 3) * 2;
        float x0 = oac[nf][0] * inv0, x1 = oac[nf][1] * inv0;
        float y0 = oac[nf][2] * inv1, y1 = oac[nf][3] * inv1;
        __half hx0 = __float2half_rn(x0), hx1 = __float2half_rn(x1);
        __half hy0 = __float2half_rn(y0), hy1 = __float2half_rn(y1);
        size_t o0 = (rowM0 * DM + col) >> 1;
        size_t o1 = ((rowM0 + 8) * DM + col) >> 1;
        __half2 hp0 = __halves2half2(hx0, hx1);
        __half2 hp1 = __halves2half2(hy0, hy1);
        reinterpret_cast<uint32_t*>(Ch)[o0] = *reinterpret_cast<uint32_t*>(&hp0);
        reinterpret_cast<uint32_t*>(Cl)[o0] = packh(x0 - __half2float(hx0), x1 - __half2float(hx1));
        reinterpret_cast<uint32_t*>(Ch)[o1] = *reinterpret_cast<uint32_t*>(&hp1);
        reinterpret_cast<uint32_t*>(Cl)[o1] = packh(y0 - __half2float(hy0), y1 - __half2float(hy1));
    }
    __threadfence();
    __syncthreads();
    if (tid == 0) atomicAdd(&g_flagA[fbase + qt], 1);
}

// ---------------------------------------------------------------------------
// Fused mega-kernel: QKV gemm tiles -> attention -> out-proj, flag-synced.
// ---------------------------------------------------------------------------
__global__ __launch_bounds__(256, 2)
void fused_mega(const float* __restrict__ bo, float* __restrict__ out)
{
    extern __shared__ __align__(128) char smc[];
    const int bid = blockIdx.x;

    if (bid < 768) {
        const int nt = bid % 24, y = bid / 24;
        const int sblk = 15 - (y >> 1), bq = y & 1;
        const int m0 = ((bq << 4) + sblk) << 7;
        gemm_tile(g_ah, g_al, g_wc, nullptr,
                  g_qh, g_kh, g_vh, g_vl, g_rope,
                  NQKV, 3, nullptr, m0, nt << 7, smc);
        __threadfence();
        __syncthreads();
        if (threadIdx.x == 0) atomicAdd(&g_flagM[m0 >> 7], 1);
    } else if (bid < 1792) {
        attn_tile(bid - 768, g_qh, g_kh, g_vh, g_vl, g_ah, g_al, smc);
    } else {
        const int o = bid - 1792;
        const int mi = o >> 4, nb = o & 15;
        const int qtm = 15 - (mi >> 1), bm = mi & 1;
        const int m0 = ((bm << 4) + qtm) << 7;
        spin_ge(&g_flagA[m0 >> 7], 32);
        gemm_tile(g_ah, g_al, g_wo, out,
                  nullptr, nullptr, nullptr, nullptr, nullptr,
                  DM, 0, bo, m0, nb << 7, smc);
    }
}

// ---------------------------------------------------------------------------
// ONE prep launch: weight transposes (single fp16) + hs split (fp16 hi/lo)
// + rope table + flag zeroing.
// ---------------------------------------------------------------------------
__global__ void prep_all(const float* __restrict__ hs,
                         const float* __restrict__ Wq, const float* __restrict__ Wk,
                         const float* __restrict__ Wv, const float* __restrict__ Wo,
                         __half* __restrict__ Ah, __half* __restrict__ Al,
                         __half* __restrict__ Tc, __half* __restrict__ To,
                         float2* __restrict__ rope)
{
    int bx = blockIdx.x;
    const int tid = threadIdx.y * 32 + threadIdx.x;
    if (bx >= 161) {
        const int c = (bx - 161) * 64 + blockIdx.y;
        const size_t base4 = ((size_t)c * 2048) / 4;
#pragma unroll
        for (int u = 0; u < 2; u++) {
            size_t i = base4 + u * 256 + tid;
            float4 v = reinterpret_cast<const float4*>(hs)[i];
            float f[4] = {v.x, v.y, v.z, v.w};
            __half hh[4], ll[4];
#pragma unroll
            for (int j = 0; j < 4; j++) {
                hh[j] = __float2half_rn(f[j]);
                ll[j] = __float2half_rn(f[j] - __half2float(hh[j]));
            }
            reinterpret_cast<uint2*>(Ah)[i] = *reinterpret_cast<uint2*>(hh);
            reinterpret_cast<uint2*>(Al)[i] = *reinterpret_cast<uint2*>(ll);
        }
        return;
    }
    if (bx == 160) {
        if (blockIdx.y == 0) {
            if (tid < 32)      g_flagM[tid] = 0;
            else if (tid < 64) g_flagA[tid - 32] = 0;
        }
        int idx = (blockIdx.y * 256 + tid) * 4;
#pragma unroll
        for (int j = 0; j < 4; j++) {
            int id = idx + j;
            int s = id >> 5, pair = id & 31;
            float inv = powf(10000.f, -(float)(2 * pair) * (1.f / 64.f));
            float sn, c;
            sincosf((float)s * inv, &sn, &c);
            rope[id] = make_float2(c, sn);
        }
        return;
    }
    __shared__ float t[32][33];
    const float* W;
    __half* Th;
    int N, rowoff;
    if (bx < 64)       { W = Wq; N = 2048; rowoff = 0;    Th = Tc; }
    else if (bx < 80)  { W = Wk; N = 512;  rowoff = 2048; Th = Tc; bx -= 64; }
    else if (bx < 96)  { W = Wv; N = 512;  rowoff = 2560; Th = Tc; bx -= 80; }
    else               { W = Wo; N = 2048; rowoff = 0;    Th = To; bx -= 96; }
    const int n0 = bx * 32, k0 = blockIdx.y * 32;
    const int tx = threadIdx.x, ty = threadIdx.y;
#pragma unroll
    for (int i = 0; i < 4; i++)
        t[ty + 8 * i][tx] = W[(size_t)(k0 + ty + 8 * i) * N + n0 + tx];
    __syncthreads();
#pragma unroll
    for (int i = 0; i < 4; i++) {
        float v = t[tx][ty + 8 * i];
        size_t o = (size_t)(rowoff + n0 + ty + 8 * i) * DM + k0 + tx;
        Th[o] = __float2half_rn(v);
    }
}

// ---------------------------------------------------------------------------
extern "C" void kernel_launch(void* const* d_in, const int* in_sizes, int n_in,
                              void* d_out, int out_size)
{
    const float* hs = (const float*)d_in[0];
    const float* Wq = (const float*)d_in[1];
    const float* Wk = (const float*)d_in[2];
    const float* Wv = (const float*)d_in[3];
    const float* Wo = (const float*)d_in[4];
    const float* bo = (const float*)d_in[5];
    float* out = (float*)d_out;

    __half *ah, *al, *wc, *wo;
    float2* rope;
    cudaGetSymbolAddress((void**)&ah, g_ah);
    cudaGetSymbolAddress((void**)&al, g_al);
    cudaGetSymbolAddress((void**)&wc, g_wc);
    cudaGetSymbolAddress((void**)&wo, g_wo);
    cudaGetSymbolAddress((void**)&rope, g_rope);

    const int mega_smem = 3 * 24576;   // 73728 (gemm); attention uses 64K of it
    cudaFuncSetAttribute(fused_mega, cudaFuncAttributeMaxDynamicSharedMemorySize, mega_smem);

    // launch 1: all prep concurrently
    prep_all<<<dim3(225, 64), dim3(32, 8)>>>(hs, Wq, Wk, Wv, Wo,
                                             ah, al, wc, wo, rope);

    // launch 2: fused QKV-gemm -> attention -> out-proj (flag-synchronized)
    fused_mega<<<dim3(768 + 1024 + 512), 256, mega_smem>>>(bo, out);
}